// round 14
// baseline (speedup 1.0000x reference)
#include <cuda_runtime.h>
#include <cuda_fp16.h>
#include <cuda_bf16.h>
#include <math.h>
#include <stdint.h>

// Problem constants
#define BB 4
#define TT 1024
#define DD 1024
#define HH 16
#define HD 64
#define FF 4096
#define LL 12
#define VV 32000
#define MM (BB*TT)
#define BH (BB*HH)
#define SD3 (3*DD)

// ---------------- scratch ----------------------------------------------------
__device__ float  g_x   [(size_t)MM * DD];
__device__ __half g_hh  [(size_t)MM * DD];
__device__ float  g_qkv [(size_t)MM * 3 * DD];
__device__ __half g_atth[(size_t)MM * DD];
__device__ __half g_ffnh[(size_t)MM * FF];
__device__ __half g_wpkT[(size_t)LL * 3 * DD * DD];
__device__ __half g_woT [(size_t)LL * DD * DD];
__device__ __half g_w1T [(size_t)LL * FF * DD];
__device__ __half g_w2T [(size_t)LL * DD * FF];
__device__ __half g_lmwT[(size_t)VV * DD];

// ---------------- fp16 hi/lo split --------------------------------------------
__device__ __forceinline__ void split_h2(float x, float y,
                                         uint32_t& hi, uint32_t& lo) {
    __half2 h = __floats2half2_rn(x, y);
    float2 hf = __half22float2(h);
    __half2 l = __floats2half2_rn(x - hf.x, y - hf.y);
    hi = *(uint32_t*)&h;
    lo = *(uint32_t*)&l;
}

// ---------------- batched transpose + fp16 convert ---------------------------
__global__ void __launch_bounds__(256) transpose_h_kernel(
    const float* __restrict__ src, __half* __restrict__ dst, int R, int C) {
    __shared__ float t[32][33];
    const float* s = src + (size_t)blockIdx.z * R * C;
    __half* d = dst + (size_t)blockIdx.z * R * C;
    int c0 = blockIdx.x * 32, r0 = blockIdx.y * 32;
    int x = threadIdx.x, y = threadIdx.y;
    #pragma unroll
    for (int j = 0; j < 32; j += 8)
        t[y + j][x] = s[(size_t)(r0 + y + j) * C + c0 + x];
    __syncthreads();
    #pragma unroll
    for (int j = 0; j < 32; j += 8)
        d[(size_t)(c0 + y + j) * R + r0 + x] = __float2half_rn(t[x][y + j]);
}

// ---------------- embedding --------------------------------------------------
__global__ void __launch_bounds__(256) embed_kernel(
    const int* __restrict__ idx, const float* __restrict__ tok,
    const float* __restrict__ pos, float* __restrict__ x) {
    int row = blockIdx.x;
    int t = row & (TT - 1);
    int token = idx[row];
    int tid = threadIdx.x;
    float4 a = ((const float4*)(tok + (size_t)token * DD))[tid];
    float4 p = ((const float4*)(pos + (size_t)t * DD))[tid];
    float4 o; o.x = a.x + p.x; o.y = a.y + p.y; o.z = a.z + p.z; o.w = a.w + p.w;
    ((float4*)(x + (size_t)row * DD))[tid] = o;
}

// ---------------- layernorm -> fp16 (warp-shuffle reductions) -----------------
__global__ void __launch_bounds__(256) ln_kernel(
    const float* __restrict__ x, const float* __restrict__ g,
    const float* __restrict__ b, __half* __restrict__ y) {
    __shared__ float red1[8];
    __shared__ float red2[8];
    int row = blockIdx.x, tid = threadIdx.x;
    int lane = tid & 31, wid = tid >> 5;
    float4 v = ((const float4*)(x + (size_t)row * DD))[tid];
    float s = v.x + v.y + v.z + v.w;
    #pragma unroll
    for (int o = 16; o > 0; o >>= 1) s += __shfl_xor_sync(0xffffffff, s, o);
    if (lane == 0) red1[wid] = s;
    __syncthreads();
    float tot = 0.0f;
    #pragma unroll
    for (int w = 0; w < 8; w++) tot += red1[w];
    float m = tot * (1.0f / DD);

    float dx = v.x - m, dy = v.y - m, dz = v.z - m, dw = v.w - m;
    float q = dx * dx + dy * dy + dz * dz + dw * dw;
    #pragma unroll
    for (int o = 16; o > 0; o >>= 1) q += __shfl_xor_sync(0xffffffff, q, o);
    if (lane == 0) red2[wid] = q;
    __syncthreads();
    tot = 0.0f;
    #pragma unroll
    for (int w = 0; w < 8; w++) tot += red2[w];
    float inv = rsqrtf(tot * (1.0f / DD) + 1e-5f);

    float4 gg = ((const float4*)g)[tid];
    float4 bb = ((const float4*)b)[tid];
    __half2 h0 = __floats2half2_rn(dx * inv * gg.x + bb.x, dy * inv * gg.y + bb.y);
    __half2 h1 = __floats2half2_rn(dz * inv * gg.z + bb.z, dw * inv * gg.w + bb.w);
    uint2 u; u.x = *(uint32_t*)&h0; u.y = *(uint32_t*)&h1;
    ((uint2*)(y + (size_t)row * DD))[tid] = u;
}

// ================= fp16 tensor-core GEMM: 128x128, 4 warps x 64x64, k64 ======
// 3-stage cp.async pipeline + double-buffered ldmatrix fragments.
#define ACT_NONE 0
#define ACT_GELU 1
#define HSTR 72
#define A_STG (128*HSTR)
#define B_STG (128*HSTR)
#define STG_HALFS (A_STG + B_STG)
#define NST 3
#define GH_SMEM (NST * STG_HALFS * 2)

__device__ __forceinline__ void cp16(uint32_t dst, const void* src) {
    asm volatile("cp.async.cg.shared.global [%0], [%1], 16;" :: "r"(dst), "l"(src));
}
__device__ __forceinline__ void mma_h(float d[4], const uint32_t a[4],
                                      const uint32_t b0, const uint32_t b1) {
    asm volatile(
        "mma.sync.aligned.m16n8k16.row.col.f32.f16.f16.f32 "
        "{%0,%1,%2,%3}, {%4,%5,%6,%7}, {%8,%9}, {%0,%1,%2,%3};"
        : "+f"(d[0]), "+f"(d[1]), "+f"(d[2]), "+f"(d[3])
        : "r"(a[0]), "r"(a[1]), "r"(a[2]), "r"(a[3]), "r"(b0), "r"(b1));
}
__device__ __forceinline__ void ldsm_x4(uint32_t r[4], uint32_t addr) {
    asm volatile("ldmatrix.sync.aligned.m8n8.x4.shared.b16 {%0,%1,%2,%3}, [%4];"
        : "=r"(r[0]), "=r"(r[1]), "=r"(r[2]), "=r"(r[3]) : "r"(addr));
}
__device__ __forceinline__ void ldsm_x4_t(uint32_t r[4], uint32_t addr) {
    asm volatile("ldmatrix.sync.aligned.m8n8.x4.trans.shared.b16 {%0,%1,%2,%3}, [%4];"
        : "=r"(r[0]), "=r"(r[1]), "=r"(r[2]), "=r"(r[3]) : "r"(addr));
}
__device__ __forceinline__ void gh_load_stage(
    uint32_t sb, const __half* __restrict__ A, const __half* __restrict__ Bg,
    int bm, int K, int kt, int s, int tid) {
    const __half* Ag = A + (size_t)bm * K + (size_t)kt * 64;
    const __half* Bk = Bg + (size_t)kt * 64;
    uint32_t ab = sb + s * (STG_HALFS * 2);
    uint32_t bb = ab + A_STG * 2;
    #pragma unroll
    for (int j = 0; j < 8; j++) {
        int ch = tid + j * 128;
        int r = ch >> 3, in = ch & 7;
        cp16(ab + r * 144 + in * 16, Ag + (size_t)r * K + in * 8);
        cp16(bb + r * 144 + in * 16, Bk + (size_t)r * K + in * 8);
    }
    asm volatile("cp.async.commit_group;");
}

// OUTH: 0 = fp32 out, 1 = fp16 out
template <int ACT, int OUTH>
__global__ void __launch_bounds__(128, 2) gemm_h_kernel(
    const __half* __restrict__ A, const __half* __restrict__ Bt,
    const float* __restrict__ bias, const float* __restrict__ res,
    void* __restrict__ Cv, int N, int K, long brow0) {
    extern __shared__ __half hsm[];
    uint32_t sb = (uint32_t)__cvta_generic_to_shared(hsm);
    int tid = threadIdx.x;
    int lane = tid & 31, wid = tid >> 5;
    int g = lane >> 2, c = lane & 3;
    int bm = blockIdx.y * 128, bn = blockIdx.x * 128;
    int wm = (wid >> 1) * 64, wn = (wid & 1) * 64;
    int nk = K >> 6;
    const __half* Bg = Bt + (size_t)(brow0 + bn) * K;

    uint32_t aoff[4], boff[4];
    {
        int lr = lane & 15;
        int lk = (lane >> 4) & 1;
        #pragma unroll
        for (int mi = 0; mi < 4; mi++)
            aoff[mi] = ((wm + mi * 16 + lr) * HSTR + lk * 8) * 2;
        int nr = (lane & 7) + ((lane >> 4) & 1) * 8;
        int bk = ((lane >> 3) & 1) * 8;
        #pragma unroll
        for (int nj = 0; nj < 4; nj++)
            boff[nj] = (uint32_t)(A_STG * 2) +
                       ((wn + nj * 16 + nr) * HSTR + bk) * 2;
    }

    float d[4][8][4];
    #pragma unroll
    for (int mi = 0; mi < 4; mi++)
        #pragma unroll
        for (int ni = 0; ni < 8; ni++)
            #pragma unroll
            for (int r = 0; r < 4; r++) d[mi][ni][r] = 0.0f;

    gh_load_stage(sb, A, Bg, bm, K, 0, 0, tid);
    gh_load_stage(sb, A, Bg, bm, K, 1, 1, tid);

    uint32_t af[2][4][4], bf[2][4][4];   // double-buffered fragments
    int cs = 0, ls = 2;
    for (int t = 0; t < nk; t++) {
        asm volatile("cp.async.wait_group 1;");
        __syncthreads();
        if (t + 2 < nk) {
            gh_load_stage(sb, A, Bg, bm, K, t + 2, ls, tid);
            ls = (ls == 2) ? 0 : ls + 1;
        } else {
            asm volatile("cp.async.commit_group;");
        }

        uint32_t stb = sb + (uint32_t)cs * (STG_HALFS * 2);
        cs = (cs == 2) ? 0 : cs + 1;

        // preload chunk 0 fragments
        #pragma unroll
        for (int mi = 0; mi < 4; mi++)
            ldsm_x4(af[0][mi], stb + aoff[mi]);
        #pragma unroll
        for (int nj = 0; nj < 4; nj++)
            ldsm_x4(bf[0][nj], stb + boff[nj]);

        #pragma unroll
        for (int ks = 0; ks < 4; ks++) {
            int cur = ks & 1, nxt = cur ^ 1;
            if (ks < 3) {
                #pragma unroll
                for (int mi = 0; mi < 4; mi++)
                    ldsm_x4(af[nxt][mi], stb + aoff[mi] + (ks + 1) * 32);
                #pragma unroll
                for (int nj = 0; nj < 4; nj++)
                    ldsm_x4(bf[nxt][nj], stb + boff[nj] + (ks + 1) * 32);
            }
            #pragma unroll
            for (int mi = 0; mi < 4; mi++)
                #pragma unroll
                for (int ni = 0; ni < 8; ni++)
                    mma_h(d[mi][ni], af[cur][mi],
                          bf[cur][ni >> 1][(ni & 1) * 2],
                          bf[cur][ni >> 1][(ni & 1) * 2 + 1]);
        }
    }

    #pragma unroll
    for (int mi = 0; mi < 4; mi++) {
        #pragma unroll
        for (int rr = 0; rr < 2; rr++) {
            int row = bm + wm + mi * 16 + g + rr * 8;
            size_t ro = (size_t)row * N;
            #pragma unroll
            for (int ni = 0; ni < 8; ni++) {
                int col = bn + wn + ni * 8 + 2 * c;
                float v0 = d[mi][ni][rr * 2 + 0];
                float v1 = d[mi][ni][rr * 2 + 1];
                if (bias) { v0 += bias[col]; v1 += bias[col + 1]; }
                if (ACT == ACT_GELU) {
                    v0 = 0.5f * v0 * (1.0f + erff(v0 * 0.70710678118654752f));
                    v1 = 0.5f * v1 * (1.0f + erff(v1 * 0.70710678118654752f));
                }
                if (res) { v0 += res[ro + col]; v1 += res[ro + col + 1]; }
                if (OUTH == 1) {
                    __half2 hv = __floats2half2_rn(v0, v1);
                    *(uint32_t*)((__half*)Cv + ro + col) = *(uint32_t*)&hv;
                } else {
                    float2 o; o.x = v0; o.y = v1;
                    *(float2*)((float*)Cv + ro + col) = o;
                }
            }
        }
    }
}

// ================= flash attention: fp32 in, hi/lo split at staging ==========
#define FQH 0
#define FQL (128*72)
#define FKH (2*128*72)
#define FKL (FKH + 64*72)
#define FVH (FKL + 64*72)
#define FVL (FVH + 64*72)
#define FLASH_HALFS (FVL + 64*72)
#define FLASH_SMEM_BYTES (FLASH_HALFS * 2)      // 73728 B

__global__ void __launch_bounds__(256) flash_attn_kernel(
    const float* __restrict__ qkv, __half* __restrict__ att) {
    extern __shared__ __half fsm[];
    uint32_t sb = (uint32_t)__cvta_generic_to_shared(fsm);
    int it = 7 - blockIdx.x;
    int bh = blockIdx.y;
    int b = bh >> 4, h = bh & 15;
    int tid = threadIdx.x;
    int lane = tid & 31, wid = tid >> 5;
    int g = lane >> 2, c = lane & 3;
    int wr = wid * 16;

    const float* qg = qkv + (size_t)b * TT * SD3 + DD     + h * HD;
    const float* kg = qkv + (size_t)b * TT * SD3 + 0      + h * HD;
    const float* vg = qkv + (size_t)b * TT * SD3 + 2 * DD + h * HD;

    #pragma unroll
    for (int j = 0; j < 4; j++) {
        int ch = tid + j * 256;
        int r = ch >> 3;
        int ck = (ch & 7) * 8;
        const float* p = qg + (size_t)(it * 128 + r) * SD3 + ck;
        float4 a = *(const float4*)(p);
        float4 bq = *(const float4*)(p + 4);
        uint4 hv, lv;
        split_h2(a.x,  a.y,  hv.x, lv.x);
        split_h2(a.z,  a.w,  hv.y, lv.y);
        split_h2(bq.x, bq.y, hv.z, lv.z);
        split_h2(bq.z, bq.w, hv.w, lv.w);
        *(uint4*)&fsm[FQH + r * 72 + ck] = hv;
        *(uint4*)&fsm[FQL + r * 72 + ck] = lv;
    }
    __syncthreads();

    uint32_t qoff = ((wr + (lane & 15)) * 72 + ((lane >> 4) & 1) * 8) * 2;
    uint32_t koff[4], voff[4];
    {
        int nr = (lane & 7) + ((lane >> 4) & 1) * 8;
        int bk = ((lane >> 3) & 1) * 8;
        int vr = (lane & 7) + ((lane >> 3) & 1) * 8;
        int vc = ((lane >> 4) & 1) * 8;
        #pragma unroll
        for (int nj = 0; nj < 4; nj++) {
            koff[nj] = ((nr + nj * 16) * 72 + bk) * 2;
            voff[nj] = (vr * 72 + nj * 16 + vc) * 2;
        }
    }

    float oacc[8][4];
    #pragma unroll
    for (int ni = 0; ni < 8; ni++)
        #pragma unroll
        for (int r = 0; r < 4; r++) oacc[ni][r] = 0.0f;
    float mrow[2] = {-INFINITY, -INFINITY};
    float lrow[2] = {0.0f, 0.0f};

    const int njt = 2 * it + 2;
    const float scale = 0.03125f;

    for (int jt = 0; jt < njt; jt++) {
        #pragma unroll
        for (int j = 0; j < 2; j++) {
            int ch = tid + j * 256;
            int r = ch >> 3;
            int ck = (ch & 7) * 8;
            size_t go = (size_t)(jt * 64 + r) * SD3 + ck;
            {
                const float* p = kg + go;
                float4 a = *(const float4*)(p);
                float4 bq = *(const float4*)(p + 4);
                uint4 hv, lv;
                split_h2(a.x,  a.y,  hv.x, lv.x);
                split_h2(a.z,  a.w,  hv.y, lv.y);
                split_h2(bq.x, bq.y, hv.z, lv.z);
                split_h2(bq.z, bq.w, hv.w, lv.w);
                *(uint4*)&fsm[FKH + r * 72 + ck] = hv;
                *(uint4*)&fsm[FKL + r * 72 + ck] = lv;
            }
            {
                const float* p = vg + go;
                float4 a = *(const float4*)(p);
                float4 bq = *(const float4*)(p + 4);
                uint4 hv, lv;
                split_h2(a.x,  a.y,  hv.x, lv.x);
                split_h2(a.z,  a.w,  hv.y, lv.y);
                split_h2(bq.x, bq.y, hv.z, lv.z);
                split_h2(bq.z, bq.w, hv.w, lv.w);
                *(uint4*)&fsm[FVH + r * 72 + ck] = hv;
                *(uint4*)&fsm[FVL + r * 72 + ck] = lv;
            }
        }
        __syncthreads();

        float sacc[8][4];
        #pragma unroll
        for (int ni = 0; ni < 8; ni++)
            #pragma unroll
            for (int r = 0; r < 4; r++) sacc[ni][r] = 0.0f;

        #pragma unroll
        for (int s = 0; s < 4; s++) {
            uint32_t qa[4], qb[4];
            ldsm_x4(qa, sb + FQH * 2 + qoff + s * 32);
            ldsm_x4(qb, sb + FQL * 2 + qoff + s * 32);
            #pragma unroll
            for (int nj = 0; nj < 4; nj++) {
                uint32_t kh[4], kl[4];
                ldsm_x4(kh, sb + FKH * 2 + koff[nj] + s * 32);
                ldsm_x4(kl, sb + FKL * 2 + koff[nj] + s * 32);
                mma_h(sacc[2 * nj],     qa, kh[0], kh[1]);
                mma_h(sacc[2 * nj],     qb, kh[0], kh[1]);
                mma_h(sacc[2 * nj],     qa, kl[0], kl[1]);
                mma_h(sacc[2 * nj + 1], qa, kh[2], kh[3]);
                mma_h(sacc[2 * nj + 1], qb, kh[2], kh[3]);
                mma_h(sacc[2 * nj + 1], qa, kl[2], kl[3]);
            }
        }

        bool full = (jt * 64 + 63) <= (it * 128 + wr);
        #pragma unroll
        for (int ni = 0; ni < 8; ni++)
            #pragma unroll
            for (int r = 0; r < 4; r++) {
                float v = sacc[ni][r] * scale;
                if (!full) {
                    int gi = it * 128 + wr + g + (r >> 1) * 8;
                    int gj = jt * 64 + ni * 8 + 2 * c + (r & 1);
                    if (gj > gi) v = -INFINITY;
                }
                sacc[ni][r] = v;
            }

        #pragma unroll
        for (int rr = 0; rr < 2; rr++) {
            float mt = -INFINITY;
            #pragma unroll
            for (int ni = 0; ni < 8; ni++) {
                mt = fmaxf(mt, sacc[ni][rr * 2 + 0]);
                mt = fmaxf(mt, sacc[ni][rr * 2 + 1]);
            }
            mt = fmaxf(mt, __shfl_xor_sync(0xffffffff, mt, 1));
            mt = fmaxf(mt, __shfl_xor_sync(0xffffffff, mt, 2));
            float mnew = fmaxf(mrow[rr], mt);
            float alpha = __expf(mrow[rr] - mnew);
            mrow[rr] = mnew;
            float rs = 0.0f;
            #pragma unroll
            for (int ni = 0; ni < 8; ni++) {
                float p0 = __expf(sacc[ni][rr * 2 + 0] - mnew);
                float p1 = __expf(sacc[ni][rr * 2 + 1] - mnew);
                sacc[ni][rr * 2 + 0] = p0;
                sacc[ni][rr * 2 + 1] = p1;
                rs += p0 + p1;
            }
            rs += __shfl_xor_sync(0xffffffff, rs, 1);
            rs += __shfl_xor_sync(0xffffffff, rs, 2);
            lrow[rr] = lrow[rr] * alpha + rs;
            #pragma unroll
            for (int ni = 0; ni < 8; ni++) {
                oacc[ni][rr * 2 + 0] *= alpha;
                oacc[ni][rr * 2 + 1] *= alpha;
            }
        }

        #pragma unroll
        for (int s = 0; s < 4; s++) {
            uint32_t phi[4], plo[4];
            split_h2(sacc[2 * s][0],     sacc[2 * s][1],     phi[0], plo[0]);
            split_h2(sacc[2 * s][2],     sacc[2 * s][3],     phi[1], plo[1]);
            split_h2(sacc[2 * s + 1][0], sacc[2 * s + 1][1], phi[2], plo[2]);
            split_h2(sacc[2 * s + 1][2], sacc[2 * s + 1][3], phi[3], plo[3]);
            #pragma unroll
            for (int nj = 0; nj < 4; nj++) {
                uint32_t vh[4], vl[4];
                ldsm_x4_t(vh, sb + FVH * 2 + voff[nj] + s * 2304);
                ldsm_x4_t(vl, sb + FVL * 2 + voff[nj] + s * 2304);
                mma_h(oacc[2 * nj],     phi, vh[0], vh[1]);
                mma_h(oacc[2 * nj],     plo, vh[0], vh[1]);
                mma_h(oacc[2 * nj],     phi, vl[0], vl[1]);
                mma_h(oacc[2 * nj + 1], phi, vh[2], vh[3]);
                mma_h(oacc[2 * nj + 1], plo, vh[2], vh[3]);
                mma_h(oacc[2 * nj + 1], phi, vl[2], vl[3]);
            }
        }
        __syncthreads();
    }

    #pragma unroll
    for (int rr = 0; rr < 2; rr++) {
        float inv = 1.0f / lrow[rr];
        int gi = it * 128 + wr + g + rr * 8;
        __half* orow = att + (size_t)(b * TT + gi) * DD + h * HD + 2 * c;
        #pragma unroll
        for (int ni = 0; ni < 8; ni++) {
            __half2 hv = __floats2half2_rn(oacc[ni][rr * 2 + 0] * inv,
                                           oacc[ni][rr * 2 + 1] * inv);
            *(uint32_t*)(orow + ni * 8) = *(uint32_t*)&hv;
        }
    }
}

// ---------------- host helpers -----------------------------------------------
static void launch_gh(const __half* A, const __half* Bt, long brow0,
                      const float* bias, const float* res,
                      void* C, int N, int K, int mode) {
    dim3 grid(N / 128, MM / 128);
    if (mode == 1)
        gemm_h_kernel<ACT_GELU, 1><<<grid, 128, GH_SMEM>>>(A, Bt, bias, res, C, N, K, brow0);
    else
        gemm_h_kernel<ACT_NONE, 0><<<grid, 128, GH_SMEM>>>(A, Bt, bias, res, C, N, K, brow0);
}

extern "C" void kernel_launch(void* const* d_in, const int* in_sizes, int n_in,
                              void* d_out, int out_size) {
    const int*   idx  = (const int*)d_in[0];
    const float* tok  = (const float*)d_in[1];
    const float* pos  = (const float*)d_in[2];
    const float* wqkv = (const float*)d_in[3];
    const float* wo   = (const float*)d_in[4];
    const float* bo   = (const float*)d_in[5];
    const float* ln1g = (const float*)d_in[6];
    const float* ln1b = (const float*)d_in[7];
    const float* ln2g = (const float*)d_in[8];
    const float* ln2b = (const float*)d_in[9];
    const float* w1   = (const float*)d_in[10];
    const float* b1   = (const float*)d_in[11];
    const float* w2   = (const float*)d_in[12];
    const float* b2   = (const float*)d_in[13];
    const float* lnfg = (const float*)d_in[14];
    const float* lnfb = (const float*)d_in[15];
    const float* lmw  = (const float*)d_in[16];
    const float* lmb  = (const float*)d_in[17];
    float* out = (float*)d_out;

    float *x, *qkv;
    __half *hh, *atth, *ffnh, *wpkT, *woT, *w1T, *w2T, *lmwT;
    cudaGetSymbolAddress((void**)&x,    g_x);
    cudaGetSymbolAddress((void**)&hh,   g_hh);
    cudaGetSymbolAddress((void**)&qkv,  g_qkv);
    cudaGetSymbolAddress((void**)&atth, g_atth);
    cudaGetSymbolAddress((void**)&ffnh, g_ffnh);
    cudaGetSymbolAddress((void**)&wpkT, g_wpkT);
    cudaGetSymbolAddress((void**)&woT,  g_woT);
    cudaGetSymbolAddress((void**)&w1T,  g_w1T);
    cudaGetSymbolAddress((void**)&w2T,  g_w2T);
    cudaGetSymbolAddress((void**)&lmwT, g_lmwT);

    cudaFuncSetAttribute(gemm_h_kernel<ACT_NONE, 0>,
                         cudaFuncAttributeMaxDynamicSharedMemorySize, GH_SMEM);
    cudaFuncSetAttribute(gemm_h_kernel<ACT_GELU, 1>,
                         cudaFuncAttributeMaxDynamicSharedMemorySize, GH_SMEM);
    cudaFuncSetAttribute(flash_attn_kernel,
                         cudaFuncAttributeMaxDynamicSharedMemorySize, FLASH_SMEM_BYTES);

    dim3 tb(32, 8);
    // Launch #4 is the one ncu profiles -> keep it the QKV GEMM.
    embed_kernel<<<MM, 256>>>(idx, tok, pos, x);                       // 1
    transpose_h_kernel<<<dim3(2, 32, 576), tb>>>(wqkv, wpkT, DD, HD);  // 2
    ln_kernel<<<MM, 256>>>(x, ln1g, ln1b, hh);                         // 3
    launch_gh(hh, wpkT, 0L, nullptr, nullptr, qkv, 3 * DD, DD, 0);     // 4 <- profiled
    flash_attn_kernel<<<dim3(8, 64), 256, FLASH_SMEM_BYTES>>>(qkv, atth);
    transpose_h_kernel<<<dim3(32, 32, LL), tb>>>(wo, woT, DD, DD);
    launch_gh(atth, woT, 0L, bo, x, x, DD, DD, 0);
    transpose_h_kernel<<<dim3(128, 32, LL), tb>>>(w1, w1T, DD, FF);
    transpose_h_kernel<<<dim3(32, 128, LL), tb>>>(w2, w2T, FF, DD);
    transpose_h_kernel<<<dim3(1000, 32, 1), tb>>>(lmw, lmwT, DD, VV);
    ln_kernel<<<MM, 256>>>(x, ln2g, ln2b, hh);
    launch_gh(hh, w1T, 0L, b1, nullptr, ffnh, FF, DD, 1);
    launch_gh(ffnh, w2T, 0L, b2, x, x, DD, FF, 0);

    for (int l = 1; l < LL; l++) {
        ln_kernel<<<MM, 256>>>(x, ln1g + l * DD, ln1b + l * DD, hh);
        launch_gh(hh, wpkT, (long)l * 3 * DD, nullptr, nullptr, qkv, 3 * DD, DD, 0);
        flash_attn_kernel<<<dim3(8, 64), 256, FLASH_SMEM_BYTES>>>(qkv, atth);
        launch_gh(atth, woT, (long)l * DD, bo + l * DD, x, x, DD, DD, 0);
        ln_kernel<<<MM, 256>>>(x, ln2g + l * DD, ln2b + l * DD, hh);
        launch_gh(hh, w1T, (long)l * FF, b1 + l * FF, nullptr, ffnh, FF, DD, 1);
        launch_gh(ffnh, w2T, (long)l * DD, b2 + l * DD, x, x, DD, FF, 0);
    }

    ln_kernel<<<MM, 256>>>(x, lnfg, lnfb, hh);
    launch_gh(hh, lmwT, 0L, lmb, nullptr, out, VV, DD, 0);
}

// round 15
// speedup vs baseline: 1.0378x; 1.0378x over previous
#include <cuda_runtime.h>
#include <cuda_fp16.h>
#include <cuda_bf16.h>
#include <math.h>
#include <stdint.h>

// Problem constants
#define BB 4
#define TT 1024
#define DD 1024
#define HH 16
#define HD 64
#define FF 4096
#define LL 12
#define VV 32000
#define MM (BB*TT)
#define BH (BB*HH)
#define SD3 (3*DD)

// ---------------- scratch ----------------------------------------------------
__device__ float  g_x   [(size_t)MM * DD];
__device__ __half g_hh  [(size_t)MM * DD];
__device__ float  g_qkv [(size_t)MM * 3 * DD];
__device__ __half g_atth[(size_t)MM * DD];
__device__ __half g_ffnh[(size_t)MM * FF];
__device__ __half g_wpkT[(size_t)LL * 3 * DD * DD];
__device__ __half g_woT [(size_t)LL * DD * DD];
__device__ __half g_w1T [(size_t)LL * FF * DD];
__device__ __half g_w2T [(size_t)LL * DD * FF];
__device__ __half g_lmwT[(size_t)VV * DD];

// ---------------- fp16 hi/lo split --------------------------------------------
__device__ __forceinline__ void split_h2(float x, float y,
                                         uint32_t& hi, uint32_t& lo) {
    __half2 h = __floats2half2_rn(x, y);
    float2 hf = __half22float2(h);
    __half2 l = __floats2half2_rn(x - hf.x, y - hf.y);
    hi = *(uint32_t*)&h;
    lo = *(uint32_t*)&l;
}

// ---------------- batched transpose + fp16 convert ---------------------------
__global__ void __launch_bounds__(256) transpose_h_kernel(
    const float* __restrict__ src, __half* __restrict__ dst, int R, int C) {
    __shared__ float t[32][33];
    const float* s = src + (size_t)blockIdx.z * R * C;
    __half* d = dst + (size_t)blockIdx.z * R * C;
    int c0 = blockIdx.x * 32, r0 = blockIdx.y * 32;
    int x = threadIdx.x, y = threadIdx.y;
    #pragma unroll
    for (int j = 0; j < 32; j += 8)
        t[y + j][x] = s[(size_t)(r0 + y + j) * C + c0 + x];
    __syncthreads();
    #pragma unroll
    for (int j = 0; j < 32; j += 8)
        d[(size_t)(c0 + y + j) * R + r0 + x] = __float2half_rn(t[x][y + j]);
}

// ---------------- embedding --------------------------------------------------
__global__ void __launch_bounds__(256) embed_kernel(
    const int* __restrict__ idx, const float* __restrict__ tok,
    const float* __restrict__ pos, float* __restrict__ x) {
    int row = blockIdx.x;
    int t = row & (TT - 1);
    int token = idx[row];
    int tid = threadIdx.x;
    float4 a = ((const float4*)(tok + (size_t)token * DD))[tid];
    float4 p = ((const float4*)(pos + (size_t)t * DD))[tid];
    float4 o; o.x = a.x + p.x; o.y = a.y + p.y; o.z = a.z + p.z; o.w = a.w + p.w;
    ((float4*)(x + (size_t)row * DD))[tid] = o;
}

// ---------------- layernorm -> fp16 (warp-shuffle reductions) -----------------
__global__ void __launch_bounds__(256) ln_kernel(
    const float* __restrict__ x, const float* __restrict__ g,
    const float* __restrict__ b, __half* __restrict__ y) {
    __shared__ float red1[8];
    __shared__ float red2[8];
    int row = blockIdx.x, tid = threadIdx.x;
    int lane = tid & 31, wid = tid >> 5;
    float4 v = ((const float4*)(x + (size_t)row * DD))[tid];
    float s = v.x + v.y + v.z + v.w;
    #pragma unroll
    for (int o = 16; o > 0; o >>= 1) s += __shfl_xor_sync(0xffffffff, s, o);
    if (lane == 0) red1[wid] = s;
    __syncthreads();
    float tot = 0.0f;
    #pragma unroll
    for (int w = 0; w < 8; w++) tot += red1[w];
    float m = tot * (1.0f / DD);

    float dx = v.x - m, dy = v.y - m, dz = v.z - m, dw = v.w - m;
    float q = dx * dx + dy * dy + dz * dz + dw * dw;
    #pragma unroll
    for (int o = 16; o > 0; o >>= 1) q += __shfl_xor_sync(0xffffffff, q, o);
    if (lane == 0) red2[wid] = q;
    __syncthreads();
    tot = 0.0f;
    #pragma unroll
    for (int w = 0; w < 8; w++) tot += red2[w];
    float inv = rsqrtf(tot * (1.0f / DD) + 1e-5f);

    float4 gg = ((const float4*)g)[tid];
    float4 bb = ((const float4*)b)[tid];
    __half2 h0 = __floats2half2_rn(dx * inv * gg.x + bb.x, dy * inv * gg.y + bb.y);
    __half2 h1 = __floats2half2_rn(dz * inv * gg.z + bb.z, dw * inv * gg.w + bb.w);
    uint2 u; u.x = *(uint32_t*)&h0; u.y = *(uint32_t*)&h1;
    ((uint2*)(y + (size_t)row * DD))[tid] = u;
}

// ================= fp16 tensor-core GEMM: 128x128, 4 warps x 64x64, k64 ======
// (R13 mainloop — ptxas schedules fragment pipelining itself.)
#define ACT_NONE 0
#define ACT_GELU 1
#define HSTR 72
#define A_STG (128*HSTR)
#define B_STG (128*HSTR)
#define STG_HALFS (A_STG + B_STG)
#define NST 3
#define GH_SMEM (NST * STG_HALFS * 2)

__device__ __forceinline__ void cp16(uint32_t dst, const void* src) {
    asm volatile("cp.async.cg.shared.global [%0], [%1], 16;" :: "r"(dst), "l"(src));
}
__device__ __forceinline__ void mma_h(float d[4], const uint32_t a[4],
                                      const uint32_t b0, const uint32_t b1) {
    asm volatile(
        "mma.sync.aligned.m16n8k16.row.col.f32.f16.f16.f32 "
        "{%0,%1,%2,%3}, {%4,%5,%6,%7}, {%8,%9}, {%0,%1,%2,%3};"
        : "+f"(d[0]), "+f"(d[1]), "+f"(d[2]), "+f"(d[3])
        : "r"(a[0]), "r"(a[1]), "r"(a[2]), "r"(a[3]), "r"(b0), "r"(b1));
}
__device__ __forceinline__ void ldsm_x4(uint32_t r[4], uint32_t addr) {
    asm volatile("ldmatrix.sync.aligned.m8n8.x4.shared.b16 {%0,%1,%2,%3}, [%4];"
        : "=r"(r[0]), "=r"(r[1]), "=r"(r[2]), "=r"(r[3]) : "r"(addr));
}
__device__ __forceinline__ void ldsm_x4_t(uint32_t r[4], uint32_t addr) {
    asm volatile("ldmatrix.sync.aligned.m8n8.x4.trans.shared.b16 {%0,%1,%2,%3}, [%4];"
        : "=r"(r[0]), "=r"(r[1]), "=r"(r[2]), "=r"(r[3]) : "r"(addr));
}
__device__ __forceinline__ void gh_load_stage(
    uint32_t sb, const __half* __restrict__ A, const __half* __restrict__ Bg,
    int bm, int K, int kt, int s, int tid) {
    const __half* Ag = A + (size_t)bm * K + (size_t)kt * 64;
    const __half* Bk = Bg + (size_t)kt * 64;
    uint32_t ab = sb + s * (STG_HALFS * 2);
    uint32_t bb = ab + A_STG * 2;
    #pragma unroll
    for (int j = 0; j < 8; j++) {
        int ch = tid + j * 128;
        int r = ch >> 3, in = ch & 7;
        cp16(ab + r * 144 + in * 16, Ag + (size_t)r * K + in * 8);
        cp16(bb + r * 144 + in * 16, Bk + (size_t)r * K + in * 8);
    }
    asm volatile("cp.async.commit_group;");
}

// OUTH: 0 = fp32 out, 1 = fp16 out
template <int ACT, int OUTH>
__global__ void __launch_bounds__(128, 2) gemm_h_kernel(
    const __half* __restrict__ A, const __half* __restrict__ Bt,
    const float* __restrict__ bias, const float* __restrict__ res,
    void* __restrict__ Cv, int N, int K, long brow0) {
    extern __shared__ __half hsm[];
    uint32_t sb = (uint32_t)__cvta_generic_to_shared(hsm);
    int tid = threadIdx.x;
    int lane = tid & 31, wid = tid >> 5;
    int g = lane >> 2, c = lane & 3;
    int bm = blockIdx.y * 128, bn = blockIdx.x * 128;
    int wm = (wid >> 1) * 64, wn = (wid & 1) * 64;
    int nk = K >> 6;
    const __half* Bg = Bt + (size_t)(brow0 + bn) * K;

    uint32_t aoff[4], boff[4];
    {
        int lr = lane & 15;
        int lk = (lane >> 4) & 1;
        #pragma unroll
        for (int mi = 0; mi < 4; mi++)
            aoff[mi] = ((wm + mi * 16 + lr) * HSTR + lk * 8) * 2;
        int nr = (lane & 7) + ((lane >> 4) & 1) * 8;
        int bk = ((lane >> 3) & 1) * 8;
        #pragma unroll
        for (int nj = 0; nj < 4; nj++)
            boff[nj] = (uint32_t)(A_STG * 2) +
                       ((wn + nj * 16 + nr) * HSTR + bk) * 2;
    }

    float d[4][8][4];
    #pragma unroll
    for (int mi = 0; mi < 4; mi++)
        #pragma unroll
        for (int ni = 0; ni < 8; ni++)
            #pragma unroll
            for (int r = 0; r < 4; r++) d[mi][ni][r] = 0.0f;

    gh_load_stage(sb, A, Bg, bm, K, 0, 0, tid);
    gh_load_stage(sb, A, Bg, bm, K, 1, 1, tid);

    int cs = 0, ls = 2;
    for (int t = 0; t < nk; t++) {
        asm volatile("cp.async.wait_group 1;");
        __syncthreads();
        if (t + 2 < nk) {
            gh_load_stage(sb, A, Bg, bm, K, t + 2, ls, tid);
            ls = (ls == 2) ? 0 : ls + 1;
        } else {
            asm volatile("cp.async.commit_group;");
        }

        uint32_t stb = sb + (uint32_t)cs * (STG_HALFS * 2);
        cs = (cs == 2) ? 0 : cs + 1;
        #pragma unroll
        for (int ks = 0; ks < 4; ks++) {
            uint32_t af[4][4], bf[4][4];
            #pragma unroll
            for (int mi = 0; mi < 4; mi++)
                ldsm_x4(af[mi], stb + aoff[mi] + ks * 32);
            #pragma unroll
            for (int nj = 0; nj < 4; nj++)
                ldsm_x4(bf[nj], stb + boff[nj] + ks * 32);
            #pragma unroll
            for (int mi = 0; mi < 4; mi++)
                #pragma unroll
                for (int ni = 0; ni < 8; ni++)
                    mma_h(d[mi][ni], af[mi], bf[ni >> 1][(ni & 1) * 2],
                          bf[ni >> 1][(ni & 1) * 2 + 1]);
        }
    }

    #pragma unroll
    for (int mi = 0; mi < 4; mi++) {
        #pragma unroll
        for (int rr = 0; rr < 2; rr++) {
            int row = bm + wm + mi * 16 + g + rr * 8;
            size_t ro = (size_t)row * N;
            #pragma unroll
            for (int ni = 0; ni < 8; ni++) {
                int col = bn + wn + ni * 8 + 2 * c;
                float v0 = d[mi][ni][rr * 2 + 0];
                float v1 = d[mi][ni][rr * 2 + 1];
                if (bias) { v0 += bias[col]; v1 += bias[col + 1]; }
                if (ACT == ACT_GELU) {
                    v0 = 0.5f * v0 * (1.0f + erff(v0 * 0.70710678118654752f));
                    v1 = 0.5f * v1 * (1.0f + erff(v1 * 0.70710678118654752f));
                }
                if (res) { v0 += res[ro + col]; v1 += res[ro + col + 1]; }
                if (OUTH == 1) {
                    __half2 hv = __floats2half2_rn(v0, v1);
                    *(uint32_t*)((__half*)Cv + ro + col) = *(uint32_t*)&hv;
                } else {
                    float2 o; o.x = v0; o.y = v1;
                    *(float2*)((float*)Cv + ro + col) = o;
                }
            }
        }
    }
}

// ================= flash attention: double-buffered K/V staging ==============
// Q hi/lo staged once; K/V hi/lo staged per-jt into alternating buffers so the
// global loads for jt+1 overlap the compute of jt. One barrier per jt.
#define FQH 0
#define FQL (128*72)
#define FKV (2*128*72)                 // start of K/V buffers (halves)
#define KVB (4*64*72)                  // halves per buffer (KH,KL,VH,VL)
#define KO_KL (64*72)
#define KO_VH (2*64*72)
#define KO_VL (3*64*72)
#define FLASH_HALFS (FKV + 2*KVB)      // 55296 halves
#define FLASH_SMEM_BYTES (FLASH_HALFS * 2)   // 110592 B

__device__ __forceinline__ void flash_stage_kv(
    __half* fsm, const float* __restrict__ kg, const float* __restrict__ vg,
    int jt, int buf, int tid) {
    int base = FKV + buf * KVB;
    #pragma unroll
    for (int j = 0; j < 2; j++) {
        int ch = tid + j * 256;
        int r = ch >> 3;
        int ck = (ch & 7) * 8;
        size_t go = (size_t)(jt * 64 + r) * SD3 + ck;
        {
            const float* p = kg + go;
            float4 a = *(const float4*)(p);
            float4 bq = *(const float4*)(p + 4);
            uint4 hv, lv;
            split_h2(a.x,  a.y,  hv.x, lv.x);
            split_h2(a.z,  a.w,  hv.y, lv.y);
            split_h2(bq.x, bq.y, hv.z, lv.z);
            split_h2(bq.z, bq.w, hv.w, lv.w);
            *(uint4*)&fsm[base + r * 72 + ck] = hv;
            *(uint4*)&fsm[base + KO_KL + r * 72 + ck] = lv;
        }
        {
            const float* p = vg + go;
            float4 a = *(const float4*)(p);
            float4 bq = *(const float4*)(p + 4);
            uint4 hv, lv;
            split_h2(a.x,  a.y,  hv.x, lv.x);
            split_h2(a.z,  a.w,  hv.y, lv.y);
            split_h2(bq.x, bq.y, hv.z, lv.z);
            split_h2(bq.z, bq.w, hv.w, lv.w);
            *(uint4*)&fsm[base + KO_VH + r * 72 + ck] = hv;
            *(uint4*)&fsm[base + KO_VL + r * 72 + ck] = lv;
        }
    }
}

__global__ void __launch_bounds__(256) flash_attn_kernel(
    const float* __restrict__ qkv, __half* __restrict__ att) {
    extern __shared__ __half fsm[];
    uint32_t sb = (uint32_t)__cvta_generic_to_shared(fsm);
    int it = 7 - blockIdx.x;
    int bh = blockIdx.y;
    int b = bh >> 4, h = bh & 15;
    int tid = threadIdx.x;
    int lane = tid & 31, wid = tid >> 5;
    int g = lane >> 2, c = lane & 3;
    int wr = wid * 16;

    const float* qg = qkv + (size_t)b * TT * SD3 + DD     + h * HD;
    const float* kg = qkv + (size_t)b * TT * SD3 + 0      + h * HD;
    const float* vg = qkv + (size_t)b * TT * SD3 + 2 * DD + h * HD;

    // ---- stage Q hi/lo once + first K/V tile into buffer 0 ----
    #pragma unroll
    for (int j = 0; j < 4; j++) {
        int ch = tid + j * 256;
        int r = ch >> 3;
        int ck = (ch & 7) * 8;
        const float* p = qg + (size_t)(it * 128 + r) * SD3 + ck;
        float4 a = *(const float4*)(p);
        float4 bq = *(const float4*)(p + 4);
        uint4 hv, lv;
        split_h2(a.x,  a.y,  hv.x, lv.x);
        split_h2(a.z,  a.w,  hv.y, lv.y);
        split_h2(bq.x, bq.y, hv.z, lv.z);
        split_h2(bq.z, bq.w, hv.w, lv.w);
        *(uint4*)&fsm[FQH + r * 72 + ck] = hv;
        *(uint4*)&fsm[FQL + r * 72 + ck] = lv;
    }
    flash_stage_kv(fsm, kg, vg, 0, 0, tid);
    __syncthreads();

    uint32_t qoff = ((wr + (lane & 15)) * 72 + ((lane >> 4) & 1) * 8) * 2;
    uint32_t koff[4], voff[4];
    {
        int nr = (lane & 7) + ((lane >> 4) & 1) * 8;
        int bk = ((lane >> 3) & 1) * 8;
        int vr = (lane & 7) + ((lane >> 3) & 1) * 8;
        int vc = ((lane >> 4) & 1) * 8;
        #pragma unroll
        for (int nj = 0; nj < 4; nj++) {
            koff[nj] = ((nr + nj * 16) * 72 + bk) * 2;
            voff[nj] = (vr * 72 + nj * 16 + vc) * 2;
        }
    }

    float oacc[8][4];
    #pragma unroll
    for (int ni = 0; ni < 8; ni++)
        #pragma unroll
        for (int r = 0; r < 4; r++) oacc[ni][r] = 0.0f;
    float mrow[2] = {-INFINITY, -INFINITY};
    float lrow[2] = {0.0f, 0.0f};

    const int njt = 2 * it + 2;
    const float scale = 0.03125f;

    for (int jt = 0; jt < njt; jt++) {
        int cb = jt & 1;
        // prefetch next K/V tile into the other buffer (overlaps compute)
        if (jt + 1 < njt)
            flash_stage_kv(fsm, kg, vg, jt + 1, cb ^ 1, tid);

        uint32_t kvb = sb + (uint32_t)(FKV + cb * KVB) * 2;

        // ---- S = Q K^T : 3xFP16 via ldmatrix fragments ----
        float sacc[8][4];
        #pragma unroll
        for (int ni = 0; ni < 8; ni++)
            #pragma unroll
            for (int r = 0; r < 4; r++) sacc[ni][r] = 0.0f;

        #pragma unroll
        for (int s = 0; s < 4; s++) {
            uint32_t qa[4], qb[4];
            ldsm_x4(qa, sb + FQH * 2 + qoff + s * 32);
            ldsm_x4(qb, sb + FQL * 2 + qoff + s * 32);
            #pragma unroll
            for (int nj = 0; nj < 4; nj++) {
                uint32_t kh[4], kl[4];
                ldsm_x4(kh, kvb + koff[nj] + s * 32);
                ldsm_x4(kl, kvb + (uint32_t)(KO_KL * 2) + koff[nj] + s * 32);
                mma_h(sacc[2 * nj],     qa, kh[0], kh[1]);
                mma_h(sacc[2 * nj],     qb, kh[0], kh[1]);
                mma_h(sacc[2 * nj],     qa, kl[0], kl[1]);
                mma_h(sacc[2 * nj + 1], qa, kh[2], kh[3]);
                mma_h(sacc[2 * nj + 1], qb, kh[2], kh[3]);
                mma_h(sacc[2 * nj + 1], qa, kl[2], kl[3]);
            }
        }

        bool full = (jt * 64 + 63) <= (it * 128 + wr);
        #pragma unroll
        for (int ni = 0; ni < 8; ni++)
            #pragma unroll
            for (int r = 0; r < 4; r++) {
                float v = sacc[ni][r] * scale;
                if (!full) {
                    int gi = it * 128 + wr + g + (r >> 1) * 8;
                    int gj = jt * 64 + ni * 8 + 2 * c + (r & 1);
                    if (gj > gi) v = -INFINITY;
                }
                sacc[ni][r] = v;
            }

        #pragma unroll
        for (int rr = 0; rr < 2; rr++) {
            float mt = -INFINITY;
            #pragma unroll
            for (int ni = 0; ni < 8; ni++) {
                mt = fmaxf(mt, sacc[ni][rr * 2 + 0]);
                mt = fmaxf(mt, sacc[ni][rr * 2 + 1]);
            }
            mt = fmaxf(mt, __shfl_xor_sync(0xffffffff, mt, 1));
            mt = fmaxf(mt, __shfl_xor_sync(0xffffffff, mt, 2));
            float mnew = fmaxf(mrow[rr], mt);
            float alpha = __expf(mrow[rr] - mnew);
            mrow[rr] = mnew;
            float rs = 0.0f;
            #pragma unroll
            for (int ni = 0; ni < 8; ni++) {
                float p0 = __expf(sacc[ni][rr * 2 + 0] - mnew);
                float p1 = __expf(sacc[ni][rr * 2 + 1] - mnew);
                sacc[ni][rr * 2 + 0] = p0;
                sacc[ni][rr * 2 + 1] = p1;
                rs += p0 + p1;
            }
            rs += __shfl_xor_sync(0xffffffff, rs, 1);
            rs += __shfl_xor_sync(0xffffffff, rs, 2);
            lrow[rr] = lrow[rr] * alpha + rs;
            #pragma unroll
            for (int ni = 0; ni < 8; ni++) {
                oacc[ni][rr * 2 + 0] *= alpha;
                oacc[ni][rr * 2 + 1] *= alpha;
            }
        }

        // ---- O += P V : P repacked directly from registers ----
        #pragma unroll
        for (int s = 0; s < 4; s++) {
            uint32_t phi[4], plo[4];
            split_h2(sacc[2 * s][0],     sacc[2 * s][1],     phi[0], plo[0]);
            split_h2(sacc[2 * s][2],     sacc[2 * s][3],     phi[1], plo[1]);
            split_h2(sacc[2 * s + 1][0], sacc[2 * s + 1][1], phi[2], plo[2]);
            split_h2(sacc[2 * s + 1][2], sacc[2 * s + 1][3], phi[3], plo[3]);
            #pragma unroll
            for (int nj = 0; nj < 4; nj++) {
                uint32_t vh[4], vl[4];
                ldsm_x4_t(vh, kvb + (uint32_t)(KO_VH * 2) + voff[nj] + s * 2304);
                ldsm_x4_t(vl, kvb + (uint32_t)(KO_VL * 2) + voff[nj] + s * 2304);
                mma_h(oacc[2 * nj],     phi, vh[0], vh[1]);
                mma_h(oacc[2 * nj],     plo, vh[0], vh[1]);
                mma_h(oacc[2 * nj],     phi, vl[0], vl[1]);
                mma_h(oacc[2 * nj + 1], phi, vh[2], vh[3]);
                mma_h(oacc[2 * nj + 1], plo, vh[2], vh[3]);
                mma_h(oacc[2 * nj + 1], phi, vl[2], vl[3]);
            }
        }
        __syncthreads();   // buf cb reads done; buf cb^1 writes visible
    }

    #pragma unroll
    for (int rr = 0; rr < 2; rr++) {
        float inv = 1.0f / lrow[rr];
        int gi = it * 128 + wr + g + rr * 8;
        __half* orow = att + (size_t)(b * TT + gi) * DD + h * HD + 2 * c;
        #pragma unroll
        for (int ni = 0; ni < 8; ni++) {
            __half2 hv = __floats2half2_rn(oacc[ni][rr * 2 + 0] * inv,
                                           oacc[ni][rr * 2 + 1] * inv);
            *(uint32_t*)(orow + ni * 8) = *(uint32_t*)&hv;
        }
    }
}

// ---------------- host helpers -----------------------------------------------
static void launch_gh(const __half* A, const __half* Bt, long brow0,
                      const float* bias, const float* res,
                      void* C, int N, int K, int mode) {
    dim3 grid(N / 128, MM / 128);
    if (mode == 1)
        gemm_h_kernel<ACT_GELU, 1><<<grid, 128, GH_SMEM>>>(A, Bt, bias, res, C, N, K, brow0);
    else
        gemm_h_kernel<ACT_NONE, 0><<<grid, 128, GH_SMEM>>>(A, Bt, bias, res, C, N, K, brow0);
}

extern "C" void kernel_launch(void* const* d_in, const int* in_sizes, int n_in,
                              void* d_out, int out_size) {
    const int*   idx  = (const int*)d_in[0];
    const float* tok  = (const float*)d_in[1];
    const float* pos  = (const float*)d_in[2];
    const float* wqkv = (const float*)d_in[3];
    const float* wo   = (const float*)d_in[4];
    const float* bo   = (const float*)d_in[5];
    const float* ln1g = (const float*)d_in[6];
    const float* ln1b = (const float*)d_in[7];
    const float* ln2g = (const float*)d_in[8];
    const float* ln2b = (const float*)d_in[9];
    const float* w1   = (const float*)d_in[10];
    const float* b1   = (const float*)d_in[11];
    const float* w2   = (const float*)d_in[12];
    const float* b2   = (const float*)d_in[13];
    const float* lnfg = (const float*)d_in[14];
    const float* lnfb = (const float*)d_in[15];
    const float* lmw  = (const float*)d_in[16];
    const float* lmb  = (const float*)d_in[17];
    float* out = (float*)d_out;

    float *x, *qkv;
    __half *hh, *atth, *ffnh, *wpkT, *woT, *w1T, *w2T, *lmwT;
    cudaGetSymbolAddress((void**)&x,    g_x);
    cudaGetSymbolAddress((void**)&hh,   g_hh);
    cudaGetSymbolAddress((void**)&qkv,  g_qkv);
    cudaGetSymbolAddress((void**)&atth, g_atth);
    cudaGetSymbolAddress((void**)&ffnh, g_ffnh);
    cudaGetSymbolAddress((void**)&wpkT, g_wpkT);
    cudaGetSymbolAddress((void**)&woT,  g_woT);
    cudaGetSymbolAddress((void**)&w1T,  g_w1T);
    cudaGetSymbolAddress((void**)&w2T,  g_w2T);
    cudaGetSymbolAddress((void**)&lmwT, g_lmwT);

    cudaFuncSetAttribute(gemm_h_kernel<ACT_NONE, 0>,
                         cudaFuncAttributeMaxDynamicSharedMemorySize, GH_SMEM);
    cudaFuncSetAttribute(gemm_h_kernel<ACT_GELU, 1>,
                         cudaFuncAttributeMaxDynamicSharedMemorySize, GH_SMEM);
    cudaFuncSetAttribute(flash_attn_kernel,
                         cudaFuncAttributeMaxDynamicSharedMemorySize, FLASH_SMEM_BYTES);

    dim3 tb(32, 8);
    // Launch #4 is the one ncu profiles -> keep it the QKV GEMM.
    embed_kernel<<<MM, 256>>>(idx, tok, pos, x);                       // 1
    transpose_h_kernel<<<dim3(2, 32, 576), tb>>>(wqkv, wpkT, DD, HD);  // 2
    ln_kernel<<<MM, 256>>>(x, ln1g, ln1b, hh);                         // 3
    launch_gh(hh, wpkT, 0L, nullptr, nullptr, qkv, 3 * DD, DD, 0);     // 4 <- profiled
    flash_attn_kernel<<<dim3(8, 64), 256, FLASH_SMEM_BYTES>>>(qkv, atth);
    transpose_h_kernel<<<dim3(32, 32, LL), tb>>>(wo, woT, DD, DD);
    launch_gh(atth, woT, 0L, bo, x, x, DD, DD, 0);
    transpose_h_kernel<<<dim3(128, 32, LL), tb>>>(w1, w1T, DD, FF);
    transpose_h_kernel<<<dim3(32, 128, LL), tb>>>(w2, w2T, FF, DD);
    transpose_h_kernel<<<dim3(1000, 32, 1), tb>>>(lmw, lmwT, DD, VV);
    ln_kernel<<<MM, 256>>>(x, ln2g, ln2b, hh);
    launch_gh(hh, w1T, 0L, b1, nullptr, ffnh, FF, DD, 1);
    launch_gh(ffnh, w2T, 0L, b2, x, x, DD, FF, 0);

    for (int l = 1; l < LL; l++) {
        ln_kernel<<<MM, 256>>>(x, ln1g + l * DD, ln1b + l * DD, hh);
        launch_gh(hh, wpkT, (long)l * 3 * DD, nullptr, nullptr, qkv, 3 * DD, DD, 0);
        flash_attn_kernel<<<dim3(8, 64), 256, FLASH_SMEM_BYTES>>>(qkv, atth);
        launch_gh(atth, woT, (long)l * DD, bo + l * DD, x, x, DD, DD, 0);
        ln_kernel<<<MM, 256>>>(x, ln2g + l * DD, ln2b + l * DD, hh);
        launch_gh(hh, w1T, (long)l * FF, b1 + l * FF, nullptr, ffnh, FF, DD, 1);
        launch_gh(ffnh, w2T, (long)l * DD, b2 + l * DD, x, x, DD, FF, 0);
    }

    ln_kernel<<<MM, 256>>>(x, lnfg, lnfb, hh);
    launch_gh(hh, lmwT, 0L, lmb, nullptr, out, VV, DD, 0);
}

// round 16
// speedup vs baseline: 1.0610x; 1.0223x over previous
#include <cuda_runtime.h>
#include <cuda_fp16.h>
#include <cuda_bf16.h>
#include <math.h>
#include <stdint.h>

// Problem constants
#define BB 4
#define TT 1024
#define DD 1024
#define HH 16
#define HD 64
#define FF 4096
#define LL 12
#define VV 32000
#define MM (BB*TT)
#define BH (BB*HH)
#define SD3 (3*DD)

// ---------------- scratch ----------------------------------------------------
__device__ float  g_x   [(size_t)MM * DD];
__device__ __half g_hh  [(size_t)MM * DD];
__device__ float  g_qkv [(size_t)MM * 3 * DD];
__device__ __half g_atth[(size_t)MM * DD];
__device__ __half g_ffnh[(size_t)MM * FF];
__device__ __half g_wpkT[(size_t)LL * 3 * DD * DD];
__device__ __half g_woT [(size_t)LL * DD * DD];
__device__ __half g_w1T [(size_t)LL * FF * DD];
__device__ __half g_w2T [(size_t)LL * DD * FF];
__device__ __half g_lmwT[(size_t)VV * DD];

// ---------------- fp16 hi/lo split --------------------------------------------
__device__ __forceinline__ void split_h2(float x, float y,
                                         uint32_t& hi, uint32_t& lo) {
    __half2 h = __floats2half2_rn(x, y);
    float2 hf = __half22float2(h);
    __half2 l = __floats2half2_rn(x - hf.x, y - hf.y);
    hi = *(uint32_t*)&h;
    lo = *(uint32_t*)&l;
}

// ---------------- batched transpose + fp16 convert ---------------------------
__global__ void __launch_bounds__(256) transpose_h_kernel(
    const float* __restrict__ src, __half* __restrict__ dst, int R, int C) {
    __shared__ float t[32][33];
    const float* s = src + (size_t)blockIdx.z * R * C;
    __half* d = dst + (size_t)blockIdx.z * R * C;
    int c0 = blockIdx.x * 32, r0 = blockIdx.y * 32;
    int x = threadIdx.x, y = threadIdx.y;
    #pragma unroll
    for (int j = 0; j < 32; j += 8)
        t[y + j][x] = s[(size_t)(r0 + y + j) * C + c0 + x];
    __syncthreads();
    #pragma unroll
    for (int j = 0; j < 32; j += 8)
        d[(size_t)(c0 + y + j) * R + r0 + x] = __float2half_rn(t[x][y + j]);
}

// ---------------- embedding --------------------------------------------------
__global__ void __launch_bounds__(256) embed_kernel(
    const int* __restrict__ idx, const float* __restrict__ tok,
    const float* __restrict__ pos, float* __restrict__ x) {
    int row = blockIdx.x;
    int t = row & (TT - 1);
    int token = idx[row];
    int tid = threadIdx.x;
    float4 a = ((const float4*)(tok + (size_t)token * DD))[tid];
    float4 p = ((const float4*)(pos + (size_t)t * DD))[tid];
    float4 o; o.x = a.x + p.x; o.y = a.y + p.y; o.z = a.z + p.z; o.w = a.w + p.w;
    ((float4*)(x + (size_t)row * DD))[tid] = o;
}

// ---------------- layernorm -> fp16 (warp-shuffle reductions) -----------------
__global__ void __launch_bounds__(256) ln_kernel(
    const float* __restrict__ x, const float* __restrict__ g,
    const float* __restrict__ b, __half* __restrict__ y) {
    __shared__ float red1[8];
    __shared__ float red2[8];
    int row = blockIdx.x, tid = threadIdx.x;
    int lane = tid & 31, wid = tid >> 5;
    float4 v = ((const float4*)(x + (size_t)row * DD))[tid];
    float s = v.x + v.y + v.z + v.w;
    #pragma unroll
    for (int o = 16; o > 0; o >>= 1) s += __shfl_xor_sync(0xffffffff, s, o);
    if (lane == 0) red1[wid] = s;
    __syncthreads();
    float tot = 0.0f;
    #pragma unroll
    for (int w = 0; w < 8; w++) tot += red1[w];
    float m = tot * (1.0f / DD);

    float dx = v.x - m, dy = v.y - m, dz = v.z - m, dw = v.w - m;
    float q = dx * dx + dy * dy + dz * dz + dw * dw;
    #pragma unroll
    for (int o = 16; o > 0; o >>= 1) q += __shfl_xor_sync(0xffffffff, q, o);
    if (lane == 0) red2[wid] = q;
    __syncthreads();
    tot = 0.0f;
    #pragma unroll
    for (int w = 0; w < 8; w++) tot += red2[w];
    float inv = rsqrtf(tot * (1.0f / DD) + 1e-5f);

    float4 gg = ((const float4*)g)[tid];
    float4 bb = ((const float4*)b)[tid];
    __half2 h0 = __floats2half2_rn(dx * inv * gg.x + bb.x, dy * inv * gg.y + bb.y);
    __half2 h1 = __floats2half2_rn(dz * inv * gg.z + bb.z, dw * inv * gg.w + bb.w);
    uint2 u; u.x = *(uint32_t*)&h0; u.y = *(uint32_t*)&h1;
    ((uint2*)(y + (size_t)row * DD))[tid] = u;
}

// ================= fp16 tensor-core GEMM: 128x128, 4 warps x 64x64, k64 ======
#define ACT_NONE 0
#define ACT_GELU 1
#define HSTR 72
#define A_STG (128*HSTR)
#define B_STG (128*HSTR)
#define STG_HALFS (A_STG + B_STG)
#define NST 3
#define GH_SMEM (NST * STG_HALFS * 2)

__device__ __forceinline__ void cp16(uint32_t dst, const void* src) {
    asm volatile("cp.async.cg.shared.global [%0], [%1], 16;" :: "r"(dst), "l"(src));
}
__device__ __forceinline__ void mma_h(float d[4], const uint32_t a[4],
                                      const uint32_t b0, const uint32_t b1) {
    asm volatile(
        "mma.sync.aligned.m16n8k16.row.col.f32.f16.f16.f32 "
        "{%0,%1,%2,%3}, {%4,%5,%6,%7}, {%8,%9}, {%0,%1,%2,%3};"
        : "+f"(d[0]), "+f"(d[1]), "+f"(d[2]), "+f"(d[3])
        : "r"(a[0]), "r"(a[1]), "r"(a[2]), "r"(a[3]), "r"(b0), "r"(b1));
}
__device__ __forceinline__ void ldsm_x4(uint32_t r[4], uint32_t addr) {
    asm volatile("ldmatrix.sync.aligned.m8n8.x4.shared.b16 {%0,%1,%2,%3}, [%4];"
        : "=r"(r[0]), "=r"(r[1]), "=r"(r[2]), "=r"(r[3]) : "r"(addr));
}
__device__ __forceinline__ void ldsm_x4_t(uint32_t r[4], uint32_t addr) {
    asm volatile("ldmatrix.sync.aligned.m8n8.x4.trans.shared.b16 {%0,%1,%2,%3}, [%4];"
        : "=r"(r[0]), "=r"(r[1]), "=r"(r[2]), "=r"(r[3]) : "r"(addr));
}
__device__ __forceinline__ void gh_load_stage(
    uint32_t sb, const __half* __restrict__ A, const __half* __restrict__ Bg,
    int bm, int K, int kt, int s, int tid) {
    const __half* Ag = A + (size_t)bm * K + (size_t)kt * 64;
    const __half* Bk = Bg + (size_t)kt * 64;
    uint32_t ab = sb + s * (STG_HALFS * 2);
    uint32_t bb = ab + A_STG * 2;
    #pragma unroll
    for (int j = 0; j < 8; j++) {
        int ch = tid + j * 128;
        int r = ch >> 3, in = ch & 7;
        cp16(ab + r * 144 + in * 16, Ag + (size_t)r * K + in * 8);
        cp16(bb + r * 144 + in * 16, Bk + (size_t)r * K + in * 8);
    }
    asm volatile("cp.async.commit_group;");
}

// OUTH: 0 = fp32 out, 1 = fp16 out
template <int ACT, int OUTH>
__global__ void __launch_bounds__(128, 2) gemm_h_kernel(
    const __half* __restrict__ A, const __half* __restrict__ Bt,
    const float* __restrict__ bias, const float* __restrict__ res,
    void* __restrict__ Cv, int N, int K, long brow0) {
    extern __shared__ __half hsm[];
    uint32_t sb = (uint32_t)__cvta_generic_to_shared(hsm);
    int tid = threadIdx.x;
    int lane = tid & 31, wid = tid >> 5;
    int g = lane >> 2, c = lane & 3;
    int bm = blockIdx.y * 128, bn = blockIdx.x * 128;
    int wm = (wid >> 1) * 64, wn = (wid & 1) * 64;
    int nk = K >> 6;
    const __half* Bg = Bt + (size_t)(brow0 + bn) * K;

    uint32_t aoff[4], boff[4];
    {
        int lr = lane & 15;
        int lk = (lane >> 4) & 1;
        #pragma unroll
        for (int mi = 0; mi < 4; mi++)
            aoff[mi] = ((wm + mi * 16 + lr) * HSTR + lk * 8) * 2;
        int nr = (lane & 7) + ((lane >> 4) & 1) * 8;
        int bk = ((lane >> 3) & 1) * 8;
        #pragma unroll
        for (int nj = 0; nj < 4; nj++)
            boff[nj] = (uint32_t)(A_STG * 2) +
                       ((wn + nj * 16 + nr) * HSTR + bk) * 2;
    }

    float d[4][8][4];
    #pragma unroll
    for (int mi = 0; mi < 4; mi++)
        #pragma unroll
        for (int ni = 0; ni < 8; ni++)
            #pragma unroll
            for (int r = 0; r < 4; r++) d[mi][ni][r] = 0.0f;

    gh_load_stage(sb, A, Bg, bm, K, 0, 0, tid);
    gh_load_stage(sb, A, Bg, bm, K, 1, 1, tid);

    int cs = 0, ls = 2;
    for (int t = 0; t < nk; t++) {
        asm volatile("cp.async.wait_group 1;");
        __syncthreads();
        if (t + 2 < nk) {
            gh_load_stage(sb, A, Bg, bm, K, t + 2, ls, tid);
            ls = (ls == 2) ? 0 : ls + 1;
        } else {
            asm volatile("cp.async.commit_group;");
        }

        uint32_t stb = sb + (uint32_t)cs * (STG_HALFS * 2);
        cs = (cs == 2) ? 0 : cs + 1;
        #pragma unroll
        for (int ks = 0; ks < 4; ks++) {
            uint32_t af[4][4], bf[4][4];
            #pragma unroll
            for (int mi = 0; mi < 4; mi++)
                ldsm_x4(af[mi], stb + aoff[mi] + ks * 32);
            #pragma unroll
            for (int nj = 0; nj < 4; nj++)
                ldsm_x4(bf[nj], stb + boff[nj] + ks * 32);
            #pragma unroll
            for (int mi = 0; mi < 4; mi++)
                #pragma unroll
                for (int ni = 0; ni < 8; ni++)
                    mma_h(d[mi][ni], af[mi], bf[ni >> 1][(ni & 1) * 2],
                          bf[ni >> 1][(ni & 1) * 2 + 1]);
        }
    }

    #pragma unroll
    for (int mi = 0; mi < 4; mi++) {
        #pragma unroll
        for (int rr = 0; rr < 2; rr++) {
            int row = bm + wm + mi * 16 + g + rr * 8;
            size_t ro = (size_t)row * N;
            #pragma unroll
            for (int ni = 0; ni < 8; ni++) {
                int col = bn + wn + ni * 8 + 2 * c;
                float v0 = d[mi][ni][rr * 2 + 0];
                float v1 = d[mi][ni][rr * 2 + 1];
                if (bias) {
                    float2 bv = *(const float2*)(bias + col);
                    v0 += bv.x; v1 += bv.y;
                }
                if (ACT == ACT_GELU) {
                    v0 = 0.5f * v0 * (1.0f + erff(v0 * 0.70710678118654752f));
                    v1 = 0.5f * v1 * (1.0f + erff(v1 * 0.70710678118654752f));
                }
                if (res) {
                    float2 rv = *(const float2*)(res + ro + col);
                    v0 += rv.x; v1 += rv.y;
                }
                if (OUTH == 1) {
                    __half2 hv = __floats2half2_rn(v0, v1);
                    *(uint32_t*)((__half*)Cv + ro + col) = *(uint32_t*)&hv;
                } else {
                    float2 o; o.x = v0; o.y = v1;
                    *(float2*)((float*)Cv + ro + col) = o;
                }
            }
        }
    }
}

// ================= flash attention: fp32 in, hi/lo split at staging ==========
// (R13 version — single-buffer, 73.7 KB smem.)
#define FQH 0
#define FQL (128*72)
#define FKH (2*128*72)
#define FKL (FKH + 64*72)
#define FVH (FKL + 64*72)
#define FVL (FVH + 64*72)
#define FLASH_HALFS (FVL + 64*72)
#define FLASH_SMEM_BYTES (FLASH_HALFS * 2)      // 73728 B

__global__ void __launch_bounds__(256) flash_attn_kernel(
    const float* __restrict__ qkv, __half* __restrict__ att) {
    extern __shared__ __half fsm[];
    uint32_t sb = (uint32_t)__cvta_generic_to_shared(fsm);
    int it = 7 - blockIdx.x;
    int bh = blockIdx.y;
    int b = bh >> 4, h = bh & 15;
    int tid = threadIdx.x;
    int lane = tid & 31, wid = tid >> 5;
    int g = lane >> 2, c = lane & 3;
    int wr = wid * 16;

    const float* qg = qkv + (size_t)b * TT * SD3 + DD     + h * HD;
    const float* kg = qkv + (size_t)b * TT * SD3 + 0      + h * HD;
    const float* vg = qkv + (size_t)b * TT * SD3 + 2 * DD + h * HD;

    #pragma unroll
    for (int j = 0; j < 4; j++) {
        int ch = tid + j * 256;
        int r = ch >> 3;
        int ck = (ch & 7) * 8;
        const float* p = qg + (size_t)(it * 128 + r) * SD3 + ck;
        float4 a = *(const float4*)(p);
        float4 bq = *(const float4*)(p + 4);
        uint4 hv, lv;
        split_h2(a.x,  a.y,  hv.x, lv.x);
        split_h2(a.z,  a.w,  hv.y, lv.y);
        split_h2(bq.x, bq.y, hv.z, lv.z);
        split_h2(bq.z, bq.w, hv.w, lv.w);
        *(uint4*)&fsm[FQH + r * 72 + ck] = hv;
        *(uint4*)&fsm[FQL + r * 72 + ck] = lv;
    }
    __syncthreads();

    uint32_t qoff = ((wr + (lane & 15)) * 72 + ((lane >> 4) & 1) * 8) * 2;
    uint32_t koff[4], voff[4];
    {
        int nr = (lane & 7) + ((lane >> 4) & 1) * 8;
        int bk = ((lane >> 3) & 1) * 8;
        int vr = (lane & 7) + ((lane >> 3) & 1) * 8;
        int vc = ((lane >> 4) & 1) * 8;
        #pragma unroll
        for (int nj = 0; nj < 4; nj++) {
            koff[nj] = ((nr + nj * 16) * 72 + bk) * 2;
            voff[nj] = (vr * 72 + nj * 16 + vc) * 2;
        }
    }

    float oacc[8][4];
    #pragma unroll
    for (int ni = 0; ni < 8; ni++)
        #pragma unroll
        for (int r = 0; r < 4; r++) oacc[ni][r] = 0.0f;
    float mrow[2] = {-INFINITY, -INFINITY};
    float lrow[2] = {0.0f, 0.0f};

    const int njt = 2 * it + 2;
    const float scale = 0.03125f;

    for (int jt = 0; jt < njt; jt++) {
        #pragma unroll
        for (int j = 0; j < 2; j++) {
            int ch = tid + j * 256;
            int r = ch >> 3;
            int ck = (ch & 7) * 8;
            size_t go = (size_t)(jt * 64 + r) * SD3 + ck;
            {
                const float* p = kg + go;
                float4 a = *(const float4*)(p);
                float4 bq = *(const float4*)(p + 4);
                uint4 hv, lv;
                split_h2(a.x,  a.y,  hv.x, lv.x);
                split_h2(a.z,  a.w,  hv.y, lv.y);
                split_h2(bq.x, bq.y, hv.z, lv.z);
                split_h2(bq.z, bq.w, hv.w, lv.w);
                *(uint4*)&fsm[FKH + r * 72 + ck] = hv;
                *(uint4*)&fsm[FKL + r * 72 + ck] = lv;
            }
            {
                const float* p = vg + go;
                float4 a = *(const float4*)(p);
                float4 bq = *(const float4*)(p + 4);
                uint4 hv, lv;
                split_h2(a.x,  a.y,  hv.x, lv.x);
                split_h2(a.z,  a.w,  hv.y, lv.y);
                split_h2(bq.x, bq.y, hv.z, lv.z);
                split_h2(bq.z, bq.w, hv.w, lv.w);
                *(uint4*)&fsm[FVH + r * 72 + ck] = hv;
                *(uint4*)&fsm[FVL + r * 72 + ck] = lv;
            }
        }
        __syncthreads();

        float sacc[8][4];
        #pragma unroll
        for (int ni = 0; ni < 8; ni++)
            #pragma unroll
            for (int r = 0; r < 4; r++) sacc[ni][r] = 0.0f;

        #pragma unroll
        for (int s = 0; s < 4; s++) {
            uint32_t qa[4], qb[4];
            ldsm_x4(qa, sb + FQH * 2 + qoff + s * 32);
            ldsm_x4(qb, sb + FQL * 2 + qoff + s * 32);
            #pragma unroll
            for (int nj = 0; nj < 4; nj++) {
                uint32_t kh[4], kl[4];
                ldsm_x4(kh, sb + FKH * 2 + koff[nj] + s * 32);
                ldsm_x4(kl, sb + FKL * 2 + koff[nj] + s * 32);
                mma_h(sacc[2 * nj],     qa, kh[0], kh[1]);
                mma_h(sacc[2 * nj],     qb, kh[0], kh[1]);
                mma_h(sacc[2 * nj],     qa, kl[0], kl[1]);
                mma_h(sacc[2 * nj + 1], qa, kh[2], kh[3]);
                mma_h(sacc[2 * nj + 1], qb, kh[2], kh[3]);
                mma_h(sacc[2 * nj + 1], qa, kl[2], kl[3]);
            }
        }

        bool full = (jt * 64 + 63) <= (it * 128 + wr);
        #pragma unroll
        for (int ni = 0; ni < 8; ni++)
            #pragma unroll
            for (int r = 0; r < 4; r++) {
                float v = sacc[ni][r] * scale;
                if (!full) {
                    int gi = it * 128 + wr + g + (r >> 1) * 8;
                    int gj = jt * 64 + ni * 8 + 2 * c + (r & 1);
                    if (gj > gi) v = -INFINITY;
                }
                sacc[ni][r] = v;
            }

        #pragma unroll
        for (int rr = 0; rr < 2; rr++) {
            float mt = -INFINITY;
            #pragma unroll
            for (int ni = 0; ni < 8; ni++) {
                mt = fmaxf(mt, sacc[ni][rr * 2 + 0]);
                mt = fmaxf(mt, sacc[ni][rr * 2 + 1]);
            }
            mt = fmaxf(mt, __shfl_xor_sync(0xffffffff, mt, 1));
            mt = fmaxf(mt, __shfl_xor_sync(0xffffffff, mt, 2));
            float mnew = fmaxf(mrow[rr], mt);
            float alpha = __expf(mrow[rr] - mnew);
            mrow[rr] = mnew;
            float rs = 0.0f;
            #pragma unroll
            for (int ni = 0; ni < 8; ni++) {
                float p0 = __expf(sacc[ni][rr * 2 + 0] - mnew);
                float p1 = __expf(sacc[ni][rr * 2 + 1] - mnew);
                sacc[ni][rr * 2 + 0] = p0;
                sacc[ni][rr * 2 + 1] = p1;
                rs += p0 + p1;
            }
            rs += __shfl_xor_sync(0xffffffff, rs, 1);
            rs += __shfl_xor_sync(0xffffffff, rs, 2);
            lrow[rr] = lrow[rr] * alpha + rs;
            #pragma unroll
            for (int ni = 0; ni < 8; ni++) {
                oacc[ni][rr * 2 + 0] *= alpha;
                oacc[ni][rr * 2 + 1] *= alpha;
            }
        }

        #pragma unroll
        for (int s = 0; s < 4; s++) {
            uint32_t phi[4], plo[4];
            split_h2(sacc[2 * s][0],     sacc[2 * s][1],     phi[0], plo[0]);
            split_h2(sacc[2 * s][2],     sacc[2 * s][3],     phi[1], plo[1]);
            split_h2(sacc[2 * s + 1][0], sacc[2 * s + 1][1], phi[2], plo[2]);
            split_h2(sacc[2 * s + 1][2], sacc[2 * s + 1][3], phi[3], plo[3]);
            #pragma unroll
            for (int nj = 0; nj < 4; nj++) {
                uint32_t vh[4], vl[4];
                ldsm_x4_t(vh, sb + FVH * 2 + voff[nj] + s * 2304);
                ldsm_x4_t(vl, sb + FVL * 2 + voff[nj] + s * 2304);
                mma_h(oacc[2 * nj],     phi, vh[0], vh[1]);
                mma_h(oacc[2 * nj],     plo, vh[0], vh[1]);
                mma_h(oacc[2 * nj],     phi, vl[0], vl[1]);
                mma_h(oacc[2 * nj + 1], phi, vh[2], vh[3]);
                mma_h(oacc[2 * nj + 1], plo, vh[2], vh[3]);
                mma_h(oacc[2 * nj + 1], phi, vl[2], vl[3]);
            }
        }
        __syncthreads();
    }

    #pragma unroll
    for (int rr = 0; rr < 2; rr++) {
        float inv = 1.0f / lrow[rr];
        int gi = it * 128 + wr + g + rr * 8;
        __half* orow = att + (size_t)(b * TT + gi) * DD + h * HD + 2 * c;
        #pragma unroll
        for (int ni = 0; ni < 8; ni++) {
            __half2 hv = __floats2half2_rn(oacc[ni][rr * 2 + 0] * inv,
                                           oacc[ni][rr * 2 + 1] * inv);
            *(uint32_t*)(orow + ni * 8) = *(uint32_t*)&hv;
        }
    }
}

// ---------------- host helpers -----------------------------------------------
static void launch_gh(const __half* A, const __half* Bt, long brow0,
                      const float* bias, const float* res,
                      void* C, int N, int K, int mode) {
    dim3 grid(N / 128, MM / 128);
    if (mode == 1)
        gemm_h_kernel<ACT_GELU, 1><<<grid, 128, GH_SMEM>>>(A, Bt, bias, res, C, N, K, brow0);
    else
        gemm_h_kernel<ACT_NONE, 0><<<grid, 128, GH_SMEM>>>(A, Bt, bias, res, C, N, K, brow0);
}

extern "C" void kernel_launch(void* const* d_in, const int* in_sizes, int n_in,
                              void* d_out, int out_size) {
    const int*   idx  = (const int*)d_in[0];
    const float* tok  = (const float*)d_in[1];
    const float* pos  = (const float*)d_in[2];
    const float* wqkv = (const float*)d_in[3];
    const float* wo   = (const float*)d_in[4];
    const float* bo   = (const float*)d_in[5];
    const float* ln1g = (const float*)d_in[6];
    const float* ln1b = (const float*)d_in[7];
    const float* ln2g = (const float*)d_in[8];
    const float* ln2b = (const float*)d_in[9];
    const float* w1   = (const float*)d_in[10];
    const float* b1   = (const float*)d_in[11];
    const float* w2   = (const float*)d_in[12];
    const float* b2   = (const float*)d_in[13];
    const float* lnfg = (const float*)d_in[14];
    const float* lnfb = (const float*)d_in[15];
    const float* lmw  = (const float*)d_in[16];
    const float* lmb  = (const float*)d_in[17];
    float* out = (float*)d_out;

    float *x, *qkv;
    __half *hh, *atth, *ffnh, *wpkT, *woT, *w1T, *w2T, *lmwT;
    cudaGetSymbolAddress((void**)&x,    g_x);
    cudaGetSymbolAddress((void**)&hh,   g_hh);
    cudaGetSymbolAddress((void**)&qkv,  g_qkv);
    cudaGetSymbolAddress((void**)&atth, g_atth);
    cudaGetSymbolAddress((void**)&ffnh, g_ffnh);
    cudaGetSymbolAddress((void**)&wpkT, g_wpkT);
    cudaGetSymbolAddress((void**)&woT,  g_woT);
    cudaGetSymbolAddress((void**)&w1T,  g_w1T);
    cudaGetSymbolAddress((void**)&w2T,  g_w2T);
    cudaGetSymbolAddress((void**)&lmwT, g_lmwT);

    cudaFuncSetAttribute(gemm_h_kernel<ACT_NONE, 0>,
                         cudaFuncAttributeMaxDynamicSharedMemorySize, GH_SMEM);
    cudaFuncSetAttribute(gemm_h_kernel<ACT_GELU, 1>,
                         cudaFuncAttributeMaxDynamicSharedMemorySize, GH_SMEM);
    cudaFuncSetAttribute(flash_attn_kernel,
                         cudaFuncAttributeMaxDynamicSharedMemorySize, FLASH_SMEM_BYTES);

    dim3 tb(32, 8);
    // Launch #4 is the one ncu profiles -> keep it the QKV GEMM.
    embed_kernel<<<MM, 256>>>(idx, tok, pos, x);                       // 1
    transpose_h_kernel<<<dim3(2, 32, 576), tb>>>(wqkv, wpkT, DD, HD);  // 2
    ln_kernel<<<MM, 256>>>(x, ln1g, ln1b, hh);                         // 3
    launch_gh(hh, wpkT, 0L, nullptr, nullptr, qkv, 3 * DD, DD, 0);     // 4 <- profiled
    flash_attn_kernel<<<dim3(8, 64), 256, FLASH_SMEM_BYTES>>>(qkv, atth);
    transpose_h_kernel<<<dim3(32, 32, LL), tb>>>(wo, woT, DD, DD);
    launch_gh(atth, woT, 0L, bo, x, x, DD, DD, 0);
    transpose_h_kernel<<<dim3(128, 32, LL), tb>>>(w1, w1T, DD, FF);
    transpose_h_kernel<<<dim3(32, 128, LL), tb>>>(w2, w2T, FF, DD);
    transpose_h_kernel<<<dim3(1000, 32, 1), tb>>>(lmw, lmwT, DD, VV);
    ln_kernel<<<MM, 256>>>(x, ln2g, ln2b, hh);
    launch_gh(hh, w1T, 0L, b1, nullptr, ffnh, FF, DD, 1);
    launch_gh(ffnh, w2T, 0L, b2, x, x, DD, FF, 0);

    for (int l = 1; l < LL; l++) {
        ln_kernel<<<MM, 256>>>(x, ln1g + l * DD, ln1b + l * DD, hh);
        launch_gh(hh, wpkT, (long)l * 3 * DD, nullptr, nullptr, qkv, 3 * DD, DD, 0);
        flash_attn_kernel<<<dim3(8, 64), 256, FLASH_SMEM_BYTES>>>(qkv, atth);
        launch_gh(atth, woT, (long)l * DD, bo + l * DD, x, x, DD, DD, 0);
        ln_kernel<<<MM, 256>>>(x, ln2g + l * DD, ln2b + l * DD, hh);
        launch_gh(hh, w1T, (long)l * FF, b1 + l * FF, nullptr, ffnh, FF, DD, 1);
        launch_gh(ffnh, w2T, (long)l * DD, b2 + l * DD, x, x, DD, FF, 0);
    }

    ln_kernel<<<MM, 256>>>(x, lnfg, lnfb, hh);
    launch_gh(hh, lmwT, 0L, lmb, nullptr, out, VV, DD, 0);
}

// round 17
// speedup vs baseline: 1.0703x; 1.0088x over previous
#include <cuda_runtime.h>
#include <cuda_fp16.h>
#include <cuda_bf16.h>
#include <math.h>
#include <stdint.h>

// Problem constants
#define BB 4
#define TT 1024
#define DD 1024
#define HH 16
#define HD 64
#define FF 4096
#define LL 12
#define VV 32000
#define MM (BB*TT)
#define BH (BB*HH)
#define SD3 (3*DD)

// ---------------- scratch ----------------------------------------------------
__device__ float  g_x   [(size_t)MM * DD];
__device__ __half g_hh  [(size_t)MM * DD];
__device__ float  g_qkv [(size_t)MM * 3 * DD];
__device__ __half g_atth[(size_t)MM * DD];
__device__ __half g_ffnh[(size_t)MM * FF];
__device__ __half g_wpkT[(size_t)LL * 3 * DD * DD];
__device__ __half g_woT [(size_t)LL * DD * DD];
__device__ __half g_w1T [(size_t)LL * FF * DD];
__device__ __half g_w2T [(size_t)LL * DD * FF];
__device__ __half g_lmwT[(size_t)VV * DD];

// ---------------- fp16 hi/lo split --------------------------------------------
__device__ __forceinline__ void split_h2(float x, float y,
                                         uint32_t& hi, uint32_t& lo) {
    __half2 h = __floats2half2_rn(x, y);
    float2 hf = __half22float2(h);
    __half2 l = __floats2half2_rn(x - hf.x, y - hf.y);
    hi = *(uint32_t*)&h;
    lo = *(uint32_t*)&l;
}

// ---------------- batched transpose + fp16 convert ---------------------------
__global__ void __launch_bounds__(256) transpose_h_kernel(
    const float* __restrict__ src, __half* __restrict__ dst, int R, int C) {
    __shared__ float t[32][33];
    const float* s = src + (size_t)blockIdx.z * R * C;
    __half* d = dst + (size_t)blockIdx.z * R * C;
    int c0 = blockIdx.x * 32, r0 = blockIdx.y * 32;
    int x = threadIdx.x, y = threadIdx.y;
    #pragma unroll
    for (int j = 0; j < 32; j += 8)
        t[y + j][x] = s[(size_t)(r0 + y + j) * C + c0 + x];
    __syncthreads();
    #pragma unroll
    for (int j = 0; j < 32; j += 8)
        d[(size_t)(c0 + y + j) * R + r0 + x] = __float2half_rn(t[x][y + j]);
}

// ---------------- embedding --------------------------------------------------
__global__ void __launch_bounds__(256) embed_kernel(
    const int* __restrict__ idx, const float* __restrict__ tok,
    const float* __restrict__ pos, float* __restrict__ x) {
    int row = blockIdx.x;
    int t = row & (TT - 1);
    int token = idx[row];
    int tid = threadIdx.x;
    float4 a = ((const float4*)(tok + (size_t)token * DD))[tid];
    float4 p = ((const float4*)(pos + (size_t)t * DD))[tid];
    float4 o; o.x = a.x + p.x; o.y = a.y + p.y; o.z = a.z + p.z; o.w = a.w + p.w;
    ((float4*)(x + (size_t)row * DD))[tid] = o;
}

// ---------------- layernorm -> fp16 (warp-shuffle reductions) -----------------
__global__ void __launch_bounds__(256) ln_kernel(
    const float* __restrict__ x, const float* __restrict__ g,
    const float* __restrict__ b, __half* __restrict__ y) {
    __shared__ float red1[8];
    __shared__ float red2[8];
    int row = blockIdx.x, tid = threadIdx.x;
    int lane = tid & 31, wid = tid >> 5;
    float4 v = ((const float4*)(x + (size_t)row * DD))[tid];
    float s = v.x + v.y + v.z + v.w;
    #pragma unroll
    for (int o = 16; o > 0; o >>= 1) s += __shfl_xor_sync(0xffffffff, s, o);
    if (lane == 0) red1[wid] = s;
    __syncthreads();
    float tot = 0.0f;
    #pragma unroll
    for (int w = 0; w < 8; w++) tot += red1[w];
    float m = tot * (1.0f / DD);

    float dx = v.x - m, dy = v.y - m, dz = v.z - m, dw = v.w - m;
    float q = dx * dx + dy * dy + dz * dz + dw * dw;
    #pragma unroll
    for (int o = 16; o > 0; o >>= 1) q += __shfl_xor_sync(0xffffffff, q, o);
    if (lane == 0) red2[wid] = q;
    __syncthreads();
    tot = 0.0f;
    #pragma unroll
    for (int w = 0; w < 8; w++) tot += red2[w];
    float inv = rsqrtf(tot * (1.0f / DD) + 1e-5f);

    float4 gg = ((const float4*)g)[tid];
    float4 bb = ((const float4*)b)[tid];
    __half2 h0 = __floats2half2_rn(dx * inv * gg.x + bb.x, dy * inv * gg.y + bb.y);
    __half2 h1 = __floats2half2_rn(dz * inv * gg.z + bb.z, dw * inv * gg.w + bb.w);
    uint2 u; u.x = *(uint32_t*)&h0; u.y = *(uint32_t*)&h1;
    ((uint2*)(y + (size_t)row * DD))[tid] = u;
}

// ================= fp16 tensor-core GEMM: 128x128, 4 warps x 64x64, k64 ======
#define ACT_NONE 0
#define ACT_GELU 1
#define HSTR 72
#define A_STG (128*HSTR)
#define B_STG (128*HSTR)
#define STG_HALFS (A_STG + B_STG)
#define NST 3
#define GH_SMEM (NST * STG_HALFS * 2)

__device__ __forceinline__ void cp16(uint32_t dst, const void* src) {
    asm volatile("cp.async.cg.shared.global [%0], [%1], 16;" :: "r"(dst), "l"(src));
}
__device__ __forceinline__ void mma_h(float d[4], const uint32_t a[4],
                                      const uint32_t b0, const uint32_t b1) {
    asm volatile(
        "mma.sync.aligned.m16n8k16.row.col.f32.f16.f16.f32 "
        "{%0,%1,%2,%3}, {%4,%5,%6,%7}, {%8,%9}, {%0,%1,%2,%3};"
        : "+f"(d[0]), "+f"(d[1]), "+f"(d[2]), "+f"(d[3])
        : "r"(a[0]), "r"(a[1]), "r"(a[2]), "r"(a[3]), "r"(b0), "r"(b1));
}
__device__ __forceinline__ void ldsm_x4(uint32_t r[4], uint32_t addr) {
    asm volatile("ldmatrix.sync.aligned.m8n8.x4.shared.b16 {%0,%1,%2,%3}, [%4];"
        : "=r"(r[0]), "=r"(r[1]), "=r"(r[2]), "=r"(r[3]) : "r"(addr));
}
__device__ __forceinline__ void ldsm_x4_t(uint32_t r[4], uint32_t addr) {
    asm volatile("ldmatrix.sync.aligned.m8n8.x4.trans.shared.b16 {%0,%1,%2,%3}, [%4];"
        : "=r"(r[0]), "=r"(r[1]), "=r"(r[2]), "=r"(r[3]) : "r"(addr));
}
__device__ __forceinline__ void gh_load_stage(
    uint32_t sb, const __half* __restrict__ A, const __half* __restrict__ Bg,
    int bm, int K, int kt, int s, int tid) {
    const __half* Ag = A + (size_t)bm * K + (size_t)kt * 64;
    const __half* Bk = Bg + (size_t)kt * 64;
    uint32_t ab = sb + s * (STG_HALFS * 2);
    uint32_t bb = ab + A_STG * 2;
    #pragma unroll
    for (int j = 0; j < 8; j++) {
        int ch = tid + j * 128;
        int r = ch >> 3, in = ch & 7;
        cp16(ab + r * 144 + in * 16, Ag + (size_t)r * K + in * 8);
        cp16(bb + r * 144 + in * 16, Bk + (size_t)r * K + in * 8);
    }
    asm volatile("cp.async.commit_group;");
}

// OUTH: 0 = fp32 out, 1 = fp16 out
template <int ACT, int OUTH>
__global__ void __launch_bounds__(128, 2) gemm_h_kernel(
    const __half* __restrict__ A, const __half* __restrict__ Bt,
    const float* __restrict__ bias, const float* __restrict__ res,
    void* __restrict__ Cv, int N, int K, long brow0) {
    extern __shared__ __half hsm[];
    uint32_t sb = (uint32_t)__cvta_generic_to_shared(hsm);
    int tid = threadIdx.x;
    int lane = tid & 31, wid = tid >> 5;
    int g = lane >> 2, c = lane & 3;
    int bm = blockIdx.y * 128, bn = blockIdx.x * 128;
    int wm = (wid >> 1) * 64, wn = (wid & 1) * 64;
    int nk = K >> 6;
    const __half* Bg = Bt + (size_t)(brow0 + bn) * K;

    uint32_t aoff[4], boff[4];
    {
        int lr = lane & 15;
        int lk = (lane >> 4) & 1;
        #pragma unroll
        for (int mi = 0; mi < 4; mi++)
            aoff[mi] = ((wm + mi * 16 + lr) * HSTR + lk * 8) * 2;
        int nr = (lane & 7) + ((lane >> 4) & 1) * 8;
        int bk = ((lane >> 3) & 1) * 8;
        #pragma unroll
        for (int nj = 0; nj < 4; nj++)
            boff[nj] = (uint32_t)(A_STG * 2) +
                       ((wn + nj * 16 + nr) * HSTR + bk) * 2;
    }

    float d[4][8][4];
    #pragma unroll
    for (int mi = 0; mi < 4; mi++)
        #pragma unroll
        for (int ni = 0; ni < 8; ni++)
            #pragma unroll
            for (int r = 0; r < 4; r++) d[mi][ni][r] = 0.0f;

    gh_load_stage(sb, A, Bg, bm, K, 0, 0, tid);
    gh_load_stage(sb, A, Bg, bm, K, 1, 1, tid);

    int cs = 0, ls = 2;
    for (int t = 0; t < nk; t++) {
        asm volatile("cp.async.wait_group 1;");
        __syncthreads();
        if (t + 2 < nk) {
            gh_load_stage(sb, A, Bg, bm, K, t + 2, ls, tid);
            ls = (ls == 2) ? 0 : ls + 1;
        } else {
            asm volatile("cp.async.commit_group;");
        }

        uint32_t stb = sb + (uint32_t)cs * (STG_HALFS * 2);
        cs = (cs == 2) ? 0 : cs + 1;
        #pragma unroll
        for (int ks = 0; ks < 4; ks++) {
            uint32_t af[4][4], bf[4][4];
            #pragma unroll
            for (int mi = 0; mi < 4; mi++)
                ldsm_x4(af[mi], stb + aoff[mi] + ks * 32);
            #pragma unroll
            for (int nj = 0; nj < 4; nj++)
                ldsm_x4(bf[nj], stb + boff[nj] + ks * 32);
            #pragma unroll
            for (int mi = 0; mi < 4; mi++)
                #pragma unroll
                for (int ni = 0; ni < 8; ni++)
                    mma_h(d[mi][ni], af[mi], bf[ni >> 1][(ni & 1) * 2],
                          bf[ni >> 1][(ni & 1) * 2 + 1]);
        }
    }

    #pragma unroll
    for (int mi = 0; mi < 4; mi++) {
        #pragma unroll
        for (int rr = 0; rr < 2; rr++) {
            int row = bm + wm + mi * 16 + g + rr * 8;
            size_t ro = (size_t)row * N;
            #pragma unroll
            for (int ni = 0; ni < 8; ni++) {
                int col = bn + wn + ni * 8 + 2 * c;
                float v0 = d[mi][ni][rr * 2 + 0];
                float v1 = d[mi][ni][rr * 2 + 1];
                if (bias) {
                    float2 bv = *(const float2*)(bias + col);
                    v0 += bv.x; v1 += bv.y;
                }
                if (ACT == ACT_GELU) {
                    v0 = 0.5f * v0 * (1.0f + erff(v0 * 0.70710678118654752f));
                    v1 = 0.5f * v1 * (1.0f + erff(v1 * 0.70710678118654752f));
                }
                if (res) {
                    float2 rv = *(const float2*)(res + ro + col);
                    v0 += rv.x; v1 += rv.y;
                }
                if (OUTH == 1) {
                    __half2 hv = __floats2half2_rn(v0, v1);
                    *(uint32_t*)((__half*)Cv + ro + col) = *(uint32_t*)&hv;
                } else {
                    float2 o; o.x = v0; o.y = v1;
                    *(float2*)((float*)Cv + ro + col) = o;
                }
            }
        }
    }
}

// ================= flash attention: fp32 in, hi/lo split at staging ==========
#define FQH 0
#define FQL (128*72)
#define FKH (2*128*72)
#define FKL (FKH + 64*72)
#define FVH (FKL + 64*72)
#define FVL (FVH + 64*72)
#define FLASH_HALFS (FVL + 64*72)
#define FLASH_SMEM_BYTES (FLASH_HALFS * 2)      // 73728 B

__global__ void __launch_bounds__(256) flash_attn_kernel(
    const float* __restrict__ qkv, __half* __restrict__ att) {
    extern __shared__ __half fsm[];
    uint32_t sb = (uint32_t)__cvta_generic_to_shared(fsm);
    int it = 7 - blockIdx.x;
    int bh = blockIdx.y;
    int b = bh >> 4, h = bh & 15;
    int tid = threadIdx.x;
    int lane = tid & 31, wid = tid >> 5;
    int g = lane >> 2, c = lane & 3;
    int wr = wid * 16;

    const float* qg = qkv + (size_t)b * TT * SD3 + DD     + h * HD;
    const float* kg = qkv + (size_t)b * TT * SD3 + 0      + h * HD;
    const float* vg = qkv + (size_t)b * TT * SD3 + 2 * DD + h * HD;

    #pragma unroll
    for (int j = 0; j < 4; j++) {
        int ch = tid + j * 256;
        int r = ch >> 3;
        int ck = (ch & 7) * 8;
        const float* p = qg + (size_t)(it * 128 + r) * SD3 + ck;
        float4 a = *(const float4*)(p);
        float4 bq = *(const float4*)(p + 4);
        uint4 hv, lv;
        split_h2(a.x,  a.y,  hv.x, lv.x);
        split_h2(a.z,  a.w,  hv.y, lv.y);
        split_h2(bq.x, bq.y, hv.z, lv.z);
        split_h2(bq.z, bq.w, hv.w, lv.w);
        *(uint4*)&fsm[FQH + r * 72 + ck] = hv;
        *(uint4*)&fsm[FQL + r * 72 + ck] = lv;
    }
    __syncthreads();

    uint32_t qoff = ((wr + (lane & 15)) * 72 + ((lane >> 4) & 1) * 8) * 2;
    uint32_t koff[4], voff[4];
    {
        int nr = (lane & 7) + ((lane >> 4) & 1) * 8;
        int bk = ((lane >> 3) & 1) * 8;
        int vr = (lane & 7) + ((lane >> 3) & 1) * 8;
        int vc = ((lane >> 4) & 1) * 8;
        #pragma unroll
        for (int nj = 0; nj < 4; nj++) {
            koff[nj] = ((nr + nj * 16) * 72 + bk) * 2;
            voff[nj] = (vr * 72 + nj * 16 + vc) * 2;
        }
    }

    float oacc[8][4];
    #pragma unroll
    for (int ni = 0; ni < 8; ni++)
        #pragma unroll
        for (int r = 0; r < 4; r++) oacc[ni][r] = 0.0f;
    float mrow[2] = {-INFINITY, -INFINITY};
    float lrow[2] = {0.0f, 0.0f};

    const int njt = 2 * it + 2;
    const float scale = 0.03125f;

    for (int jt = 0; jt < njt; jt++) {
        #pragma unroll
        for (int j = 0; j < 2; j++) {
            int ch = tid + j * 256;
            int r = ch >> 3;
            int ck = (ch & 7) * 8;
            size_t go = (size_t)(jt * 64 + r) * SD3 + ck;
            {
                const float* p = kg + go;
                float4 a = *(const float4*)(p);
                float4 bq = *(const float4*)(p + 4);
                uint4 hv, lv;
                split_h2(a.x,  a.y,  hv.x, lv.x);
                split_h2(a.z,  a.w,  hv.y, lv.y);
                split_h2(bq.x, bq.y, hv.z, lv.z);
                split_h2(bq.z, bq.w, hv.w, lv.w);
                *(uint4*)&fsm[FKH + r * 72 + ck] = hv;
                *(uint4*)&fsm[FKL + r * 72 + ck] = lv;
            }
            {
                const float* p = vg + go;
                float4 a = *(const float4*)(p);
                float4 bq = *(const float4*)(p + 4);
                uint4 hv, lv;
                split_h2(a.x,  a.y,  hv.x, lv.x);
                split_h2(a.z,  a.w,  hv.y, lv.y);
                split_h2(bq.x, bq.y, hv.z, lv.z);
                split_h2(bq.z, bq.w, hv.w, lv.w);
                *(uint4*)&fsm[FVH + r * 72 + ck] = hv;
                *(uint4*)&fsm[FVL + r * 72 + ck] = lv;
            }
        }
        __syncthreads();

        float sacc[8][4];
        #pragma unroll
        for (int ni = 0; ni < 8; ni++)
            #pragma unroll
            for (int r = 0; r < 4; r++) sacc[ni][r] = 0.0f;

        #pragma unroll
        for (int s = 0; s < 4; s++) {
            uint32_t qa[4], qb[4];
            ldsm_x4(qa, sb + FQH * 2 + qoff + s * 32);
            ldsm_x4(qb, sb + FQL * 2 + qoff + s * 32);
            #pragma unroll
            for (int nj = 0; nj < 4; nj++) {
                uint32_t kh[4], kl[4];
                ldsm_x4(kh, sb + FKH * 2 + koff[nj] + s * 32);
                ldsm_x4(kl, sb + FKL * 2 + koff[nj] + s * 32);
                mma_h(sacc[2 * nj],     qa, kh[0], kh[1]);
                mma_h(sacc[2 * nj],     qb, kh[0], kh[1]);
                mma_h(sacc[2 * nj],     qa, kl[0], kl[1]);
                mma_h(sacc[2 * nj + 1], qa, kh[2], kh[3]);
                mma_h(sacc[2 * nj + 1], qb, kh[2], kh[3]);
                mma_h(sacc[2 * nj + 1], qa, kl[2], kl[3]);
            }
        }

        bool full = (jt * 64 + 63) <= (it * 128 + wr);
        #pragma unroll
        for (int ni = 0; ni < 8; ni++)
            #pragma unroll
            for (int r = 0; r < 4; r++) {
                float v = sacc[ni][r] * scale;
                if (!full) {
                    int gi = it * 128 + wr + g + (r >> 1) * 8;
                    int gj = jt * 64 + ni * 8 + 2 * c + (r & 1);
                    if (gj > gi) v = -INFINITY;
                }
                sacc[ni][r] = v;
            }

        #pragma unroll
        for (int rr = 0; rr < 2; rr++) {
            float mt = -INFINITY;
            #pragma unroll
            for (int ni = 0; ni < 8; ni++) {
                mt = fmaxf(mt, sacc[ni][rr * 2 + 0]);
                mt = fmaxf(mt, sacc[ni][rr * 2 + 1]);
            }
            mt = fmaxf(mt, __shfl_xor_sync(0xffffffff, mt, 1));
            mt = fmaxf(mt, __shfl_xor_sync(0xffffffff, mt, 2));
            float mnew = fmaxf(mrow[rr], mt);
            float alpha = __expf(mrow[rr] - mnew);
            mrow[rr] = mnew;
            float rs = 0.0f;
            #pragma unroll
            for (int ni = 0; ni < 8; ni++) {
                float p0 = __expf(sacc[ni][rr * 2 + 0] - mnew);
                float p1 = __expf(sacc[ni][rr * 2 + 1] - mnew);
                sacc[ni][rr * 2 + 0] = p0;
                sacc[ni][rr * 2 + 1] = p1;
                rs += p0 + p1;
            }
            rs += __shfl_xor_sync(0xffffffff, rs, 1);
            rs += __shfl_xor_sync(0xffffffff, rs, 2);
            lrow[rr] = lrow[rr] * alpha + rs;
            #pragma unroll
            for (int ni = 0; ni < 8; ni++) {
                oacc[ni][rr * 2 + 0] *= alpha;
                oacc[ni][rr * 2 + 1] *= alpha;
            }
        }

        #pragma unroll
        for (int s = 0; s < 4; s++) {
            uint32_t phi[4], plo[4];
            split_h2(sacc[2 * s][0],     sacc[2 * s][1],     phi[0], plo[0]);
            split_h2(sacc[2 * s][2],     sacc[2 * s][3],     phi[1], plo[1]);
            split_h2(sacc[2 * s + 1][0], sacc[2 * s + 1][1], phi[2], plo[2]);
            split_h2(sacc[2 * s + 1][2], sacc[2 * s + 1][3], phi[3], plo[3]);
            #pragma unroll
            for (int nj = 0; nj < 4; nj++) {
                uint32_t vh[4], vl[4];
                ldsm_x4_t(vh, sb + FVH * 2 + voff[nj] + s * 2304);
                ldsm_x4_t(vl, sb + FVL * 2 + voff[nj] + s * 2304);
                mma_h(oacc[2 * nj],     phi, vh[0], vh[1]);
                mma_h(oacc[2 * nj],     plo, vh[0], vh[1]);
                mma_h(oacc[2 * nj],     phi, vl[0], vl[1]);
                mma_h(oacc[2 * nj + 1], phi, vh[2], vh[3]);
                mma_h(oacc[2 * nj + 1], plo, vh[2], vh[3]);
                mma_h(oacc[2 * nj + 1], phi, vl[2], vl[3]);
            }
        }
        __syncthreads();
    }

    #pragma unroll
    for (int rr = 0; rr < 2; rr++) {
        float inv = 1.0f / lrow[rr];
        int gi = it * 128 + wr + g + rr * 8;
        __half* orow = att + (size_t)(b * TT + gi) * DD + h * HD + 2 * c;
        #pragma unroll
        for (int ni = 0; ni < 8; ni++) {
            __half2 hv = __floats2half2_rn(oacc[ni][rr * 2 + 0] * inv,
                                           oacc[ni][rr * 2 + 1] * inv);
            *(uint32_t*)(orow + ni * 8) = *(uint32_t*)&hv;
        }
    }
}

// ---------------- host helpers -----------------------------------------------
static void launch_gh(const __half* A, const __half* Bt, long brow0,
                      const float* bias, const float* res,
                      void* C, int N, int K, int mode) {
    dim3 grid(N / 128, MM / 128);
    if (mode == 1)
        gemm_h_kernel<ACT_GELU, 1><<<grid, 128, GH_SMEM>>>(A, Bt, bias, res, C, N, K, brow0);
    else
        gemm_h_kernel<ACT_NONE, 0><<<grid, 128, GH_SMEM>>>(A, Bt, bias, res, C, N, K, brow0);
}

extern "C" void kernel_launch(void* const* d_in, const int* in_sizes, int n_in,
                              void* d_out, int out_size) {
    const int*   idx  = (const int*)d_in[0];
    const float* tok  = (const float*)d_in[1];
    const float* pos  = (const float*)d_in[2];
    const float* wqkv = (const float*)d_in[3];
    const float* wo   = (const float*)d_in[4];
    const float* bo   = (const float*)d_in[5];
    const float* ln1g = (const float*)d_in[6];
    const float* ln1b = (const float*)d_in[7];
    const float* ln2g = (const float*)d_in[8];
    const float* ln2b = (const float*)d_in[9];
    const float* w1   = (const float*)d_in[10];
    const float* b1   = (const float*)d_in[11];
    const float* w2   = (const float*)d_in[12];
    const float* b2   = (const float*)d_in[13];
    const float* lnfg = (const float*)d_in[14];
    const float* lnfb = (const float*)d_in[15];
    const float* lmw  = (const float*)d_in[16];
    const float* lmb  = (const float*)d_in[17];
    float* out = (float*)d_out;

    float *x, *qkv;
    __half *hh, *atth, *ffnh, *wpkT, *woT, *w1T, *w2T, *lmwT;
    cudaGetSymbolAddress((void**)&x,    g_x);
    cudaGetSymbolAddress((void**)&hh,   g_hh);
    cudaGetSymbolAddress((void**)&qkv,  g_qkv);
    cudaGetSymbolAddress((void**)&atth, g_atth);
    cudaGetSymbolAddress((void**)&ffnh, g_ffnh);
    cudaGetSymbolAddress((void**)&wpkT, g_wpkT);
    cudaGetSymbolAddress((void**)&woT,  g_woT);
    cudaGetSymbolAddress((void**)&w1T,  g_w1T);
    cudaGetSymbolAddress((void**)&w2T,  g_w2T);
    cudaGetSymbolAddress((void**)&lmwT, g_lmwT);

    cudaFuncSetAttribute(gemm_h_kernel<ACT_NONE, 0>,
                         cudaFuncAttributeMaxDynamicSharedMemorySize, GH_SMEM);
    cudaFuncSetAttribute(gemm_h_kernel<ACT_GELU, 1>,
                         cudaFuncAttributeMaxDynamicSharedMemorySize, GH_SMEM);
    cudaFuncSetAttribute(flash_attn_kernel,
                         cudaFuncAttributeMaxDynamicSharedMemorySize, FLASH_SMEM_BYTES);

    // Side stream + events for overlapping weight transposes with compute.
    // Created once; host-side resources only (no device memory).
    static cudaStream_t s2 = nullptr;
    static cudaEvent_t ev0 = nullptr, ev_wq = nullptr, ev_wo = nullptr,
                       ev_w1 = nullptr, ev_w2 = nullptr, ev_lm = nullptr;
    if (!s2) {
        cudaStreamCreateWithFlags(&s2, cudaStreamNonBlocking);
        cudaEventCreateWithFlags(&ev0,   cudaEventDisableTiming);
        cudaEventCreateWithFlags(&ev_wq, cudaEventDisableTiming);
        cudaEventCreateWithFlags(&ev_wo, cudaEventDisableTiming);
        cudaEventCreateWithFlags(&ev_w1, cudaEventDisableTiming);
        cudaEventCreateWithFlags(&ev_w2, cudaEventDisableTiming);
        cudaEventCreateWithFlags(&ev_lm, cudaEventDisableTiming);
    }

    dim3 tb(32, 8);
    // Fork s2 off the main stream so captures record the dependency.
    cudaEventRecord(ev0, 0);
    cudaStreamWaitEvent(s2, ev0, 0);

    // Launch #4 (kernel order) stays the QKV GEMM for the ncu profile slot.
    embed_kernel<<<MM, 256>>>(idx, tok, pos, x);                           // k1 (s0)
    transpose_h_kernel<<<dim3(2, 32, 576), tb, 0, s2>>>(wqkv, wpkT, DD, HD); // k2 (s2)
    cudaEventRecord(ev_wq, s2);
    ln_kernel<<<MM, 256>>>(x, ln1g, ln1b, hh);                             // k3 (s0)
    cudaStreamWaitEvent(0, ev_wq, 0);
    launch_gh(hh, wpkT, 0L, nullptr, nullptr, qkv, 3 * DD, DD, 0);         // k4 <- profiled
    flash_attn_kernel<<<dim3(8, 64), 256, FLASH_SMEM_BYTES>>>(qkv, atth);

    // Remaining transposes run on s2, overlapped with layer-0 compute.
    transpose_h_kernel<<<dim3(32, 32, LL), tb, 0, s2>>>(wo, woT, DD, DD);
    cudaEventRecord(ev_wo, s2);
    transpose_h_kernel<<<dim3(128, 32, LL), tb, 0, s2>>>(w1, w1T, DD, FF);
    cudaEventRecord(ev_w1, s2);
    transpose_h_kernel<<<dim3(32, 128, LL), tb, 0, s2>>>(w2, w2T, FF, DD);
    cudaEventRecord(ev_w2, s2);
    transpose_h_kernel<<<dim3(1000, 32, 1), tb, 0, s2>>>(lmw, lmwT, DD, VV);
    cudaEventRecord(ev_lm, s2);

    cudaStreamWaitEvent(0, ev_wo, 0);
    launch_gh(atth, woT, 0L, bo, x, x, DD, DD, 0);
    ln_kernel<<<MM, 256>>>(x, ln2g, ln2b, hh);
    cudaStreamWaitEvent(0, ev_w1, 0);
    launch_gh(hh, w1T, 0L, b1, nullptr, ffnh, FF, DD, 1);
    cudaStreamWaitEvent(0, ev_w2, 0);
    launch_gh(ffnh, w2T, 0L, b2, x, x, DD, FF, 0);

    for (int l = 1; l < LL; l++) {
        ln_kernel<<<MM, 256>>>(x, ln1g + l * DD, ln1b + l * DD, hh);
        launch_gh(hh, wpkT, (long)l * 3 * DD, nullptr, nullptr, qkv, 3 * DD, DD, 0);
        flash_attn_kernel<<<dim3(8, 64), 256, FLASH_SMEM_BYTES>>>(qkv, atth);
        launch_gh(atth, woT, (long)l * DD, bo + l * DD, x, x, DD, DD, 0);
        ln_kernel<<<MM, 256>>>(x, ln2g + l * DD, ln2b + l * DD, hh);
        launch_gh(hh, w1T, (long)l * FF, b1 + l * FF, nullptr, ffnh, FF, DD, 1);
        launch_gh(ffnh, w2T, (long)l * DD, b2 + l * DD, x, x, DD, FF, 0);
    }

    ln_kernel<<<MM, 256>>>(x, lnfg, lnfb, hh);
    cudaStreamWaitEvent(0, ev_lm, 0);
    launch_gh(hh, lmwT, 0L, lmb, nullptr, out, VV, DD, 0);
}